// round 2
// baseline (speedup 1.0000x reference)
#include <cuda_runtime.h>
#include <math.h>

// InformerLayer: b=4,N=32,T=256 -> B=128 seqs, L=256, C=128, H=8, E=16, DFF=512, u=k=18
#define TOK 32768
#define UK  18

__device__ float g_Aq[128], g_Bq[128], g_Ak[128], g_Bk[128], g_Av[128], g_Bv[128];
__device__ float g_c1[8], g_c2[8], g_c3[8], g_c4[8];
__device__ float g_Po[8 * 128], g_Co[128];
__device__ int   g_idx[256 * UK];
__device__ float g_alpha[TOK * 8];
__device__ float g_x1[TOK * 128];
__device__ float g_out2[TOK * 128];
__device__ float g_w1t[128 * 512];   // [c][f]
__device__ float g_w2t[512 * 128];   // [f][c]

// ------------------------------- Threefry ---------------------------------
__device__ __forceinline__ void tf_r(unsigned &x0, unsigned &x1, int r) {
    x0 += x1; x1 = (x1 << r) | (x1 >> (32 - r)); x1 ^= x0;
}
__device__ void threefry2x32(unsigned k0, unsigned k1, unsigned c0, unsigned c1,
                             unsigned &o0, unsigned &o1) {
    unsigned ks2 = k0 ^ k1 ^ 0x1BD11BDAu;
    unsigned x0 = c0 + k0, x1 = c1 + k1;
    tf_r(x0,x1,13); tf_r(x0,x1,15); tf_r(x0,x1,26); tf_r(x0,x1,6);
    x0 += k1;  x1 += ks2 + 1u;
    tf_r(x0,x1,17); tf_r(x0,x1,29); tf_r(x0,x1,16); tf_r(x0,x1,24);
    x0 += ks2; x1 += k0 + 2u;
    tf_r(x0,x1,13); tf_r(x0,x1,15); tf_r(x0,x1,26); tf_r(x0,x1,6);
    x0 += k0;  x1 += k1 + 3u;
    tf_r(x0,x1,17); tf_r(x0,x1,29); tf_r(x0,x1,16); tf_r(x0,x1,24);
    x0 += k1;  x1 += ks2 + 4u;
    tf_r(x0,x1,13); tf_r(x0,x1,15); tf_r(x0,x1,26); tf_r(x0,x1,6);
    x0 += ks2; x1 += k0 + 5u;
    o0 = x0; o1 = x1;
}

// idx = randint(key(42),(256,18),0,256): span=256 pow2 => lower_bits & 255,
// lower_bits drawn with the SECOND subkey of split(key). Original (non-
// partitionable) scheme: split counts iota(4) -> pairs (0,2),(1,3); k2 =
// (e1(0,2), e1(1,3)). bits(4608): pairs (i, 2304+i); bits[i]=o0, bits[2304+i]=o1.
__global__ void idx_kernel() {
    int i = blockIdx.x * blockDim.x + threadIdx.x;
    if (i >= 2304) return;
    unsigned a0, a1, b0, b1;
    threefry2x32(0u, 42u, 0u, 2u, a0, a1);
    threefry2x32(0u, 42u, 1u, 3u, b0, b1);
    unsigned y0, y1;
    threefry2x32(a1, b1, (unsigned)i, (unsigned)(2304 + i), y0, y1);
    g_idx[i]        = (int)(y0 & 255u);
    g_idx[2304 + i] = (int)(y1 & 255u);
}

// --------------------------- constant preparation --------------------------
__global__ void prep_consts(const float *__restrict__ mlp_w, const float *__restrict__ mlp_b,
                            const float *__restrict__ wq, const float *__restrict__ bq,
                            const float *__restrict__ wk, const float *__restrict__ bk,
                            const float *__restrict__ wv, const float *__restrict__ bv,
                            const float *__restrict__ wo, const float *__restrict__ bo) {
    int c = threadIdx.x;  // 128 threads
    float aq = 0.f, bq2 = 0.f, ak = 0.f, bk2 = 0.f, av = 0.f, bv2 = 0.f;
    for (int j = 0; j < 128; ++j) {
        float mw = mlp_w[j], mb = mlp_b[j];
        float q = wq[c * 128 + j], k = wk[c * 128 + j], v = wv[c * 128 + j];
        aq = fmaf(mw, q, aq); bq2 = fmaf(mb, q, bq2);
        ak = fmaf(mw, k, ak); bk2 = fmaf(mb, k, bk2);
        av = fmaf(mw, v, av); bv2 = fmaf(mb, v, bv2);
    }
    g_Aq[c] = aq; g_Bq[c] = bq2 + bq[c];
    g_Ak[c] = ak; g_Bk[c] = bk2 + bk[c];
    g_Av[c] = av; g_Bv[c] = bv2 + bv[c];
    __syncthreads();
    if (c < 8) {
        float c1 = 0.f, c2 = 0.f, c3 = 0.f, c4 = 0.f;
        for (int e = 0; e < 16; ++e) {
            int i = c * 16 + e;
            c1 += g_Aq[i] * g_Ak[i];
            c2 += g_Aq[i] * g_Bk[i];
            c3 += g_Bq[i] * g_Ak[i];
            c4 += g_Bq[i] * g_Bk[i];
        }
        g_c1[c] = c1; g_c2[c] = c2; g_c3[c] = c3; g_c4[c] = c4;
    }
    float co = bo[c];
    for (int j = 0; j < 128; ++j) co = fmaf(g_Bv[j], wo[c * 128 + j], co);
    g_Co[c] = co;
    for (int h = 0; h < 8; ++h) {
        float p = 0.f;
        for (int e = 0; e < 16; ++e) p = fmaf(g_Av[h * 16 + e], wo[c * 128 + h * 16 + e], p);
        g_Po[h * 128 + c] = p;
    }
}

__global__ void transpose_w(const float *__restrict__ w1, const float *__restrict__ w2) {
    int i = blockIdx.x * 256 + threadIdx.x;
    if (i < 65536) {
        int f = i >> 7, c = i & 127;
        g_w1t[c * 512 + f] = w1[i];        // w1 is [512,128]
    } else {
        int j = i - 65536;
        int c = j >> 9, f = j & 511;
        g_w2t[f * 128 + c] = w2[j];        // w2 is [128,512]
    }
}

// -------- attention: M, top-18, softmax -> alpha[tok][h]; warp = head -------
__global__ void attn_kernel(const float *__restrict__ x) {
    __shared__ float xs[256];
    __shared__ float Ms[8][256];
    int tid = threadIdx.x, lane = tid & 31, h = tid >> 5;
    int seq = blockIdx.x;
    xs[tid] = x[seq * 256 + tid];
    __syncthreads();

    float s = 0.f;
#pragma unroll
    for (int k = 0; k < 8; ++k) s += xs[lane + 32 * k];
#pragma unroll
    for (int o = 16; o > 0; o >>= 1) s += __shfl_xor_sync(0xffffffffu, s, o);
    float xbar = s * (1.0f / 256.0f);

    float c1 = g_c1[h], c2 = g_c2[h], c3 = g_c3[h], c4 = g_c4[h];

#pragma unroll
    for (int k = 0; k < 8; ++k) {
        int t = lane + 32 * k;
        float xl = xs[t];
        float mx = -3.4e38f, sm = 0.f;
#pragma unroll
        for (int j = 0; j < UK; ++j) {
            float xv = xs[g_idx[t * UK + j]];
            float sc = c1 * xl * xv + c2 * xl + c3 * xv + c4;
            mx = fmaxf(mx, sc);
            sm += sc;
        }
        Ms[h][t] = mx - sm * (1.0f / 256.0f);
        g_alpha[(seq * 256 + t) * 8 + h] = xbar;
    }
    __syncwarp();

    for (int it = 0; it < UK; ++it) {
        float bv = -3.4e38f; int bi = 256;
#pragma unroll
        for (int k = 0; k < 8; ++k) {
            int t = lane + 32 * k;
            float v = Ms[h][t];
            if (v > bv) { bv = v; bi = t; }
        }
#pragma unroll
        for (int o = 16; o > 0; o >>= 1) {
            float ov = __shfl_xor_sync(0xffffffffu, bv, o);
            int   oi = __shfl_xor_sync(0xffffffffu, bi, o);
            if (ov > bv || (ov == bv && oi < bi)) { bv = ov; bi = oi; }
        }
        int m = bi;
        if (lane == 0) Ms[h][m] = -3.4e38f;
        __syncwarp();

        float xm = xs[m];
        float sc[8], rmax = -3.4e38f;
#pragma unroll
        for (int k = 0; k < 8; ++k) {
            float xv = xs[lane + 32 * k];
            sc[k] = 0.25f * (c1 * xm * xv + c2 * xm + c3 * xv + c4);
            rmax = fmaxf(rmax, sc[k]);
        }
#pragma unroll
        for (int o = 16; o > 0; o >>= 1) rmax = fmaxf(rmax, __shfl_xor_sync(0xffffffffu, rmax, o));
        float Z = 0.f, S = 0.f;
#pragma unroll
        for (int k = 0; k < 8; ++k) {
            float e = expf(sc[k] - rmax);
            Z += e;
            S += e * xs[lane + 32 * k];
        }
#pragma unroll
        for (int o = 16; o > 0; o >>= 1) {
            Z += __shfl_xor_sync(0xffffffffu, Z, o);
            S += __shfl_xor_sync(0xffffffffu, S, o);
        }
        if (lane == 0) g_alpha[(seq * 256 + m) * 8 + h] = S / Z;
        __syncwarp();
    }
}

// ------------------- LN1: x1 = LN(h + attn_out); warp/row -------------------
__global__ void ln1_kernel(const float *__restrict__ x,
                           const float *__restrict__ mlp_w, const float *__restrict__ mlp_b,
                           const float *__restrict__ ln1g, const float *__restrict__ ln1b) {
    int w = threadIdx.x >> 5, lane = threadIdx.x & 31;
    int row = blockIdx.x * 8 + w;
    float xv = x[row];
    float av = (lane < 8) ? g_alpha[row * 8 + lane] : 0.f;
    float a[8];
#pragma unroll
    for (int hh = 0; hh < 8; ++hh) a[hh] = __shfl_sync(0xffffffffu, av, hh);

    float z[4];
#pragma unroll
    for (int j = 0; j < 4; ++j) {
        int c = lane + 32 * j;
        float zc = fmaf(xv, mlp_w[c], mlp_b[c]) + g_Co[c];
#pragma unroll
        for (int hh = 0; hh < 8; ++hh) zc = fmaf(a[hh], g_Po[hh * 128 + c], zc);
        z[j] = zc;
    }
    float s = z[0] + z[1] + z[2] + z[3];
#pragma unroll
    for (int o = 16; o > 0; o >>= 1) s += __shfl_xor_sync(0xffffffffu, s, o);
    float mu = s * (1.0f / 128.0f);
    float v = 0.f;
#pragma unroll
    for (int j = 0; j < 4; ++j) { float d = z[j] - mu; v += d * d; }
#pragma unroll
    for (int o = 16; o > 0; o >>= 1) v += __shfl_xor_sync(0xffffffffu, v, o);
    float rstd = rsqrtf(v * (1.0f / 128.0f) + 1e-5f);
#pragma unroll
    for (int j = 0; j < 4; ++j) {
        int c = lane + 32 * j;
        g_x1[row * 128 + c] = (z[j] - mu) * rstd * ln1g[c] + ln1b[c];
    }
}

// ---------- FFN + residual + LN2, fused; 16 rows/block, 40KB smem -----------
#define EROWS 16
__global__ void ffn_kernel(const float *__restrict__ b1, const float *__restrict__ b2,
                           const float *__restrict__ ln2g, const float *__restrict__ ln2b) {
    extern __shared__ float sm[];
    float *xs = sm;                  // [16][128]
    float *ts = sm + EROWS * 128;    // [16][512]
    int tid = threadIdx.x;
    int row0 = blockIdx.x * EROWS;

    for (int i = tid; i < EROWS * 128; i += 256) xs[i] = g_x1[row0 * 128 + i];
    __syncthreads();

    // T = relu(X @ W1^T + b1); thread handles ff dims f0=tid, f1=tid+256
    {
        int f0 = tid, f1 = tid + 256;
        float bb0 = b1[f0], bb1 = b1[f1];
        for (int r = 0; r < EROWS; r += 4) {
            float acc[4][2];
#pragma unroll
            for (int i = 0; i < 4; ++i) { acc[i][0] = bb0; acc[i][1] = bb1; }
            for (int cc = 0; cc < 128; cc += 4) {
                float xv[4][4];
#pragma unroll
                for (int i = 0; i < 4; ++i) {
                    float4 t = *(const float4 *)(xs + (r + i) * 128 + cc);
                    xv[i][0] = t.x; xv[i][1] = t.y; xv[i][2] = t.z; xv[i][3] = t.w;
                }
#pragma unroll
                for (int q = 0; q < 4; ++q) {
                    float w0 = g_w1t[(cc + q) * 512 + f0];
                    float w1v = g_w1t[(cc + q) * 512 + f1];
#pragma unroll
                    for (int i = 0; i < 4; ++i) {
                        acc[i][0] = fmaf(xv[i][q], w0, acc[i][0]);
                        acc[i][1] = fmaf(xv[i][q], w1v, acc[i][1]);
                    }
                }
            }
#pragma unroll
            for (int i = 0; i < 4; ++i) {
                ts[(r + i) * 512 + f0] = fmaxf(acc[i][0], 0.f);
                ts[(r + i) * 512 + f1] = fmaxf(acc[i][1], 0.f);
            }
        }
    }
    __syncthreads();

    // Y = T @ W2^T + b2 + X  (residual fused, written in-place into xs)
    {
        int c = tid & 127, rh = tid >> 7;   // rh in {0,1}, 8 rows each
        float bb = b2[c];
        for (int i = 0; i < 8; i += 2) {
            int r0 = rh * 8 + i, r1 = r0 + 1;
            float a0 = 0.f, a1 = 0.f;
            for (int f = 0; f < 512; f += 4) {
                float4 t0 = *(const float4 *)(ts + r0 * 512 + f);
                float4 t1 = *(const float4 *)(ts + r1 * 512 + f);
                float w0 = g_w2t[(f + 0) * 128 + c];
                float w1v = g_w2t[(f + 1) * 128 + c];
                float w2v = g_w2t[(f + 2) * 128 + c];
                float w3 = g_w2t[(f + 3) * 128 + c];
                a0 = fmaf(t0.x, w0, a0); a0 = fmaf(t0.y, w1v, a0);
                a0 = fmaf(t0.z, w2v, a0); a0 = fmaf(t0.w, w3, a0);
                a1 = fmaf(t1.x, w0, a1); a1 = fmaf(t1.y, w1v, a1);
                a1 = fmaf(t1.z, w2v, a1); a1 = fmaf(t1.w, w3, a1);
            }
            xs[r0 * 128 + c] = xs[r0 * 128 + c] + a0 + bb;
            xs[r1 * 128 + c] = xs[r1 * 128 + c] + a1 + bb;
        }
    }
    __syncthreads();

    // LN2 over each row; 8 warps x 2 rows
    {
        int w = tid >> 5, lane = tid & 31;
        for (int rr = w; rr < EROWS; rr += 8) {
            float z[4];
#pragma unroll
            for (int j = 0; j < 4; ++j) z[j] = xs[rr * 128 + lane + 32 * j];
            float s2 = z[0] + z[1] + z[2] + z[3];
#pragma unroll
            for (int o = 16; o > 0; o >>= 1) s2 += __shfl_xor_sync(0xffffffffu, s2, o);
            float mu = s2 * (1.0f / 128.0f);
            float v = 0.f;
#pragma unroll
            for (int j = 0; j < 4; ++j) { float d = z[j] - mu; v += d * d; }
#pragma unroll
            for (int o = 16; o > 0; o >>= 1) v += __shfl_xor_sync(0xffffffffu, v, o);
            float rstd = rsqrtf(v * (1.0f / 128.0f) + 1e-5f);
#pragma unroll
            for (int j = 0; j < 4; ++j) {
                int c = lane + 32 * j;
                g_out2[(row0 + rr) * 128 + c] = (z[j] - mu) * rstd * ln2g[c] + ln2b[c];
            }
        }
    }
}

// ----- out[b,c,t] = sum_n out2[((b*32+n)*256+t)*128 + c]; block=(t,b) -------
__global__ void reduce_kernel(float *__restrict__ out) {
    int t = blockIdx.x & 255, b = blockIdx.x >> 8;
    int c = threadIdx.x;
    float s = 0.f;
    const float *base = g_out2 + (size_t)b * 32 * 256 * 128 + t * 128 + c;
#pragma unroll 8
    for (int n = 0; n < 32; ++n) s += base[n * 256 * 128];
    out[((b * 128 + c) << 8) + t] = s;
}

extern "C" void kernel_launch(void* const* d_in, const int* in_sizes, int n_in,
                              void* d_out, int out_size) {
    const float *x     = (const float *)d_in[0];
    const float *mlp_w = (const float *)d_in[1];
    const float *mlp_b = (const float *)d_in[2];
    const float *wq = (const float *)d_in[3],  *bq = (const float *)d_in[4];
    const float *wk = (const float *)d_in[5],  *bk = (const float *)d_in[6];
    const float *wv = (const float *)d_in[7],  *bv = (const float *)d_in[8];
    const float *wo = (const float *)d_in[9],  *bo = (const float *)d_in[10];
    const float *w1 = (const float *)d_in[11], *b1 = (const float *)d_in[12];
    const float *w2 = (const float *)d_in[13], *b2 = (const float *)d_in[14];
    const float *ln1g = (const float *)d_in[15], *ln1b = (const float *)d_in[16];
    const float *ln2g = (const float *)d_in[17], *ln2b = (const float *)d_in[18];
    float *out = (float *)d_out;

    prep_consts<<<1, 128>>>(mlp_w, mlp_b, wq, bq, wk, bk, wv, bv, wo, bo);
    idx_kernel<<<9, 256>>>();
    transpose_w<<<512, 256>>>(w1, w2);
    attn_kernel<<<128, 256>>>(x);
    ln1_kernel<<<TOK / 8, 256>>>(x, mlp_w, mlp_b, ln1g, ln1b);
    ffn_kernel<<<TOK / EROWS, 256, (EROWS * 128 + EROWS * 512) * 4>>>(b1, b2, ln2g, ln2b);
    reduce_kernel<<<4 * 256, 128>>>(out);
}

// round 3
// speedup vs baseline: 3.0354x; 3.0354x over previous
#include <cuda_runtime.h>
#include <cuda_bf16.h>
#include <math.h>

// InformerLayer: b=4,N=32,T=256 -> B=128 seqs, L=256, C=128, H=8, E=16, DFF=512, u=k=18
#define TOK 32768
#define UK  18

__device__ float g_Aq[128], g_Bq[128], g_Ak[128], g_Bk[128], g_Av[128], g_Bv[128];
__device__ float g_c1[8], g_c2[8], g_c3[8], g_c4[8];
__device__ float g_Po[8 * 128], g_Co[128];
__device__ int   g_idx[256 * UK];
__device__ float g_alpha[TOK * 8];
__device__ float g_x1[TOK * 128];
__device__ unsigned g_x1bf[TOK * 64];     // bf16x2 copy of x1
__device__ float g_out2[TOK * 128];
__device__ unsigned g_w1bf[512 * 64];     // w1 [512][128] as bf16x2
__device__ unsigned g_w2bf[128 * 256];    // w2 [128][512] as bf16x2

static __device__ __forceinline__ unsigned packbf(float a, float b) {
    __nv_bfloat162 t = __floats2bfloat162_rn(a, b);
    return *reinterpret_cast<unsigned *>(&t);
}

__device__ __forceinline__ void mma16816(float &d0, float &d1, float &d2, float &d3,
                                         unsigned a0, unsigned a1, unsigned a2, unsigned a3,
                                         unsigned b0, unsigned b1) {
    asm volatile("mma.sync.aligned.m16n8k16.row.col.f32.bf16.bf16.f32 "
                 "{%0,%1,%2,%3},{%4,%5,%6,%7},{%8,%9},{%0,%1,%2,%3};"
                 : "+f"(d0), "+f"(d1), "+f"(d2), "+f"(d3)
                 : "r"(a0), "r"(a1), "r"(a2), "r"(a3), "r"(b0), "r"(b1));
}

// ------------------------------- Threefry ---------------------------------
__device__ __forceinline__ void tf_r(unsigned &x0, unsigned &x1, int r) {
    x0 += x1; x1 = (x1 << r) | (x1 >> (32 - r)); x1 ^= x0;
}
__device__ void threefry2x32(unsigned k0, unsigned k1, unsigned c0, unsigned c1,
                             unsigned &o0, unsigned &o1) {
    unsigned ks2 = k0 ^ k1 ^ 0x1BD11BDAu;
    unsigned x0 = c0 + k0, x1 = c1 + k1;
    tf_r(x0,x1,13); tf_r(x0,x1,15); tf_r(x0,x1,26); tf_r(x0,x1,6);
    x0 += k1;  x1 += ks2 + 1u;
    tf_r(x0,x1,17); tf_r(x0,x1,29); tf_r(x0,x1,16); tf_r(x0,x1,24);
    x0 += ks2; x1 += k0 + 2u;
    tf_r(x0,x1,13); tf_r(x0,x1,15); tf_r(x0,x1,26); tf_r(x0,x1,6);
    x0 += k0;  x1 += k1 + 3u;
    tf_r(x0,x1,17); tf_r(x0,x1,29); tf_r(x0,x1,16); tf_r(x0,x1,24);
    x0 += k1;  x1 += ks2 + 4u;
    tf_r(x0,x1,13); tf_r(x0,x1,15); tf_r(x0,x1,26); tf_r(x0,x1,6);
    x0 += ks2; x1 += k0 + 5u;
    o0 = x0; o1 = x1;
}

__global__ void idx_kernel() {
    int i = blockIdx.x * blockDim.x + threadIdx.x;
    if (i >= 2304) return;
    unsigned a0, a1, b0, b1;
    threefry2x32(0u, 42u, 0u, 2u, a0, a1);
    threefry2x32(0u, 42u, 1u, 3u, b0, b1);
    unsigned y0, y1;
    threefry2x32(a1, b1, (unsigned)i, (unsigned)(2304 + i), y0, y1);
    g_idx[i]        = (int)(y0 & 255u);
    g_idx[2304 + i] = (int)(y1 & 255u);
}

// --------------------------- constant preparation --------------------------
__global__ void prep_consts(const float *__restrict__ mlp_w, const float *__restrict__ mlp_b,
                            const float *__restrict__ wq, const float *__restrict__ bq,
                            const float *__restrict__ wk, const float *__restrict__ bk,
                            const float *__restrict__ wv, const float *__restrict__ bv,
                            const float *__restrict__ wo, const float *__restrict__ bo) {
    int c = threadIdx.x;  // 128 threads
    float aq = 0.f, bq2 = 0.f, ak = 0.f, bk2 = 0.f, av = 0.f, bv2 = 0.f;
    for (int j = 0; j < 128; ++j) {
        float mw = mlp_w[j], mb = mlp_b[j];
        float q = wq[c * 128 + j], k = wk[c * 128 + j], v = wv[c * 128 + j];
        aq = fmaf(mw, q, aq); bq2 = fmaf(mb, q, bq2);
        ak = fmaf(mw, k, ak); bk2 = fmaf(mb, k, bk2);
        av = fmaf(mw, v, av); bv2 = fmaf(mb, v, bv2);
    }
    g_Aq[c] = aq; g_Bq[c] = bq2 + bq[c];
    g_Ak[c] = ak; g_Bk[c] = bk2 + bk[c];
    g_Av[c] = av; g_Bv[c] = bv2 + bv[c];
    __syncthreads();
    if (c < 8) {
        float c1 = 0.f, c2 = 0.f, c3 = 0.f, c4 = 0.f;
        for (int e = 0; e < 16; ++e) {
            int i = c * 16 + e;
            c1 += g_Aq[i] * g_Ak[i];
            c2 += g_Aq[i] * g_Bk[i];
            c3 += g_Bq[i] * g_Ak[i];
            c4 += g_Bq[i] * g_Bk[i];
        }
        g_c1[c] = c1; g_c2[c] = c2; g_c3[c] = c3; g_c4[c] = c4;
    }
    float co = bo[c];
    for (int j = 0; j < 128; ++j) co = fmaf(g_Bv[j], wo[c * 128 + j], co);
    g_Co[c] = co;
    for (int h = 0; h < 8; ++h) {
        float p = 0.f;
        for (int e = 0; e < 16; ++e) p = fmaf(g_Av[h * 16 + e], wo[c * 128 + h * 16 + e], p);
        g_Po[h * 128 + c] = p;
    }
}

// weights -> bf16x2 packed
__global__ void convert_w(const float *__restrict__ w1, const float *__restrict__ w2) {
    int i = blockIdx.x * 256 + threadIdx.x;   // 65536 threads
    if (i < 32768) {
        float2 v = *(const float2 *)(w1 + 2 * i);
        g_w1bf[i] = packbf(v.x, v.y);
    } else {
        int j = i - 32768;
        float2 v = *(const float2 *)(w2 + 2 * j);
        g_w2bf[j] = packbf(v.x, v.y);
    }
}

// -------- attention: M, top-18 (per-warp), parallel softmax ----------------
__global__ void attn_kernel(const float *__restrict__ x) {
    __shared__ float xs[256];
    __shared__ float Ms[8][256];
    __shared__ int   midx[8][UK];
    int tid = threadIdx.x, lane = tid & 31, h = tid >> 5;
    int seq = blockIdx.x;
    xs[tid] = x[seq * 256 + tid];
    __syncthreads();

    float s = 0.f;
#pragma unroll
    for (int k = 0; k < 8; ++k) s += xs[lane + 32 * k];
#pragma unroll
    for (int o = 16; o > 0; o >>= 1) s += __shfl_xor_sync(0xffffffffu, s, o);
    float xbar = s * (1.0f / 256.0f);

    {
        float c1 = g_c1[h], c2 = g_c2[h], c3 = g_c3[h], c4 = g_c4[h];
#pragma unroll
        for (int k = 0; k < 8; ++k) {
            int t = lane + 32 * k;
            float xl = xs[t];
            float mx = -3.4e38f, sm = 0.f;
#pragma unroll
            for (int j = 0; j < UK; ++j) {
                float xv = xs[g_idx[t * UK + j]];
                float sc = c1 * xl * xv + c2 * xl + c3 * xv + c4;
                mx = fmaxf(mx, sc);
                sm += sc;
            }
            Ms[h][t] = mx - sm * (1.0f / 256.0f);
            g_alpha[(seq * 256 + t) * 8 + h] = xbar;
        }
    }
    __syncwarp();

    // per-warp serial top-18 argmax (cheap: no softmax inside)
    for (int it = 0; it < UK; ++it) {
        float bv = -3.4e38f; int bi = 256;
#pragma unroll
        for (int k = 0; k < 8; ++k) {
            int t = lane + 32 * k;
            float v = Ms[h][t];
            if (v > bv) { bv = v; bi = t; }
        }
#pragma unroll
        for (int o = 16; o > 0; o >>= 1) {
            float ov = __shfl_xor_sync(0xffffffffu, bv, o);
            int   oi = __shfl_xor_sync(0xffffffffu, bi, o);
            if (ov > bv || (ov == bv && oi < bi)) { bv = ov; bi = oi; }
        }
        if (lane == 0) { Ms[h][bi] = -3.4e38f; midx[h][it] = bi; }
        __syncwarp();
    }
    __syncthreads();

    // 144 softmax rows parallel across 8 warps (18 each)
    for (int p = h; p < 8 * UK; p += 8) {
        int h2 = p / UK, it = p % UK;
        int m = midx[h2][it];
        float c1 = g_c1[h2], c2 = g_c2[h2], c3 = g_c3[h2], c4 = g_c4[h2];
        float xm = xs[m];
        float sc[8], rmax = -3.4e38f;
#pragma unroll
        for (int k = 0; k < 8; ++k) {
            float xv = xs[lane + 32 * k];
            sc[k] = 0.25f * (c1 * xm * xv + c2 * xm + c3 * xv + c4);
            rmax = fmaxf(rmax, sc[k]);
        }
#pragma unroll
        for (int o = 16; o > 0; o >>= 1) rmax = fmaxf(rmax, __shfl_xor_sync(0xffffffffu, rmax, o));
        float Z = 0.f, S = 0.f;
#pragma unroll
        for (int k = 0; k < 8; ++k) {
            float e = __expf(sc[k] - rmax);
            Z += e;
            S += e * xs[lane + 32 * k];
        }
#pragma unroll
        for (int o = 16; o > 0; o >>= 1) {
            Z += __shfl_xor_sync(0xffffffffu, Z, o);
            S += __shfl_xor_sync(0xffffffffu, S, o);
        }
        if (lane == 0) g_alpha[(seq * 256 + m) * 8 + h2] = S / Z;
    }
}

// ------------------- LN1: x1 = LN(h + attn_out); warp/row -------------------
__global__ void ln1_kernel(const float *__restrict__ x,
                           const float *__restrict__ mlp_w, const float *__restrict__ mlp_b,
                           const float *__restrict__ ln1g, const float *__restrict__ ln1b) {
    int w = threadIdx.x >> 5, lane = threadIdx.x & 31;
    int row = blockIdx.x * 8 + w;
    float xv = x[row];
    float av = (lane < 8) ? g_alpha[row * 8 + lane] : 0.f;
    float a[8];
#pragma unroll
    for (int hh = 0; hh < 8; ++hh) a[hh] = __shfl_sync(0xffffffffu, av, hh);

    float z[4];
#pragma unroll
    for (int j = 0; j < 4; ++j) {
        int c = lane + 32 * j;
        float zc = fmaf(xv, mlp_w[c], mlp_b[c]) + g_Co[c];
#pragma unroll
        for (int hh = 0; hh < 8; ++hh) zc = fmaf(a[hh], g_Po[hh * 128 + c], zc);
        z[j] = zc;
    }
    float s = z[0] + z[1] + z[2] + z[3];
#pragma unroll
    for (int o = 16; o > 0; o >>= 1) s += __shfl_xor_sync(0xffffffffu, s, o);
    float mu = s * (1.0f / 128.0f);
    float v = 0.f;
#pragma unroll
    for (int j = 0; j < 4; ++j) { float d = z[j] - mu; v += d * d; }
#pragma unroll
    for (int o = 16; o > 0; o >>= 1) v += __shfl_xor_sync(0xffffffffu, v, o);
    float rstd = rsqrtf(v * (1.0f / 128.0f) + 1e-5f);
    __nv_bfloat16 *xbf = (__nv_bfloat16 *)g_x1bf;
#pragma unroll
    for (int j = 0; j < 4; ++j) {
        int c = lane + 32 * j;
        float val = (z[j] - mu) * rstd * ln1g[c] + ln1b[c];
        g_x1[row * 128 + c] = val;
        xbf[row * 128 + c] = __float2bfloat16(val);
    }
}

// ---------- FFN + residual + LN2 via mma.sync bf16; 64 rows/block ----------
// smem: sB (weight staging, padded) 34816 u32; ts (bf16 t / fp32 ys) 16640 u32
#define SB_U32 34816
#define TS_U32 16640
#define FFN_SMEM ((SB_U32 + TS_U32) * 4)

__global__ void __launch_bounds__(256, 1)
ffn_kernel(const float *__restrict__ b1, const float *__restrict__ b2,
           const float *__restrict__ ln2g, const float *__restrict__ ln2b) {
    extern __shared__ unsigned smu[];
    unsigned *sB = smu;             // GEMM1: [512][68], GEMM2: [128][260]
    unsigned *ts = smu + SB_U32;    // [64][260] bf16x2; later ys fp32 [64][128]
    int tid = threadIdx.x;
    int wid = tid >> 5, lane = tid & 31;
    int row0 = blockIdx.x * 64;
    int r = lane >> 2, q = lane & 3;
    int ms = wid & 3, nh = wid >> 2;

    // stage w1 bf16 into sB [n=512][k-u32 64, pad to 68]
    {
        const uint4 *W1 = (const uint4 *)g_w1bf;
#pragma unroll
        for (int j = 0; j < 32; ++j) {
            int idx = tid + j * 256;
            int n = idx >> 4, cc = idx & 15;
            *(uint4 *)(sB + n * 68 + cc * 4) = W1[idx];
        }
    }
    __syncthreads();

    // GEMM1: X[64,128] @ w1^T -> relu -> ts bf16 [64][512]
    unsigned a[8][4];
    {
        const unsigned *A = g_x1bf + (size_t)(row0 + ms * 16) * 64;
#pragma unroll
        for (int kk = 0; kk < 8; ++kk) {
            a[kk][0] = A[r * 64 + kk * 8 + q];
            a[kk][1] = A[(r + 8) * 64 + kk * 8 + q];
            a[kk][2] = A[r * 64 + kk * 8 + q + 4];
            a[kk][3] = A[(r + 8) * 64 + kk * 8 + q + 4];
        }
    }
    for (int t = 0; t < 32; ++t) {
        int n = nh * 256 + t * 8;
        float d0 = 0.f, d1 = 0.f, d2 = 0.f, d3 = 0.f;
        const unsigned *Bp = sB + (n + r) * 68 + q;
#pragma unroll
        for (int kk = 0; kk < 8; ++kk)
            mma16816(d0, d1, d2, d3, a[kk][0], a[kk][1], a[kk][2], a[kk][3],
                     Bp[kk * 8], Bp[kk * 8 + 4]);
        int c0 = n + q * 2;
        float2 bb = *(const float2 *)(b1 + c0);
        d0 = fmaxf(d0 + bb.x, 0.f); d1 = fmaxf(d1 + bb.y, 0.f);
        d2 = fmaxf(d2 + bb.x, 0.f); d3 = fmaxf(d3 + bb.y, 0.f);
        ts[(ms * 16 + r) * 260 + (n >> 1) + q]     = packbf(d0, d1);
        ts[(ms * 16 + r + 8) * 260 + (n >> 1) + q] = packbf(d2, d3);
    }
    __syncthreads();

    // stage w2 bf16 into sB [n=128][k-u32 256, pad to 260]
    {
        const uint4 *W2 = (const uint4 *)g_w2bf;
#pragma unroll
        for (int j = 0; j < 32; ++j) {
            int idx = tid + j * 256;
            int n = idx >> 6, cc = idx & 63;
            *(uint4 *)(sB + n * 260 + cc * 4) = W2[idx];
        }
    }
    __syncthreads();

    // GEMM2: T[64,512] @ w2^T -> y[64,128]
    float d[8][4];
#pragma unroll
    for (int t = 0; t < 8; ++t) { d[t][0] = 0.f; d[t][1] = 0.f; d[t][2] = 0.f; d[t][3] = 0.f; }
    {
        const unsigned *At = ts + (ms * 16) * 260;
#pragma unroll 4
        for (int kk = 0; kk < 32; ++kk) {
            unsigned a0 = At[r * 260 + kk * 8 + q];
            unsigned a1 = At[(r + 8) * 260 + kk * 8 + q];
            unsigned a2 = At[r * 260 + kk * 8 + q + 4];
            unsigned a3 = At[(r + 8) * 260 + kk * 8 + q + 4];
#pragma unroll
            for (int t = 0; t < 8; ++t) {
                const unsigned *Bp = sB + (nh * 64 + t * 8 + r) * 260 + kk * 8 + q;
                mma16816(d[t][0], d[t][1], d[t][2], d[t][3], a0, a1, a2, a3, Bp[0], Bp[4]);
            }
        }
    }
    __syncthreads();

    // ys = y + b2 + residual (reuse ts as fp32 [64][128])
    float *ys = (float *)ts;
#pragma unroll
    for (int t = 0; t < 8; ++t) {
        int n = nh * 64 + t * 8, c0 = n + q * 2;
        float2 bb = *(const float2 *)(b2 + c0);
        int rr = ms * 16 + r;
        float2 r0v = *(const float2 *)(g_x1 + (size_t)(row0 + rr) * 128 + c0);
        float2 r1v = *(const float2 *)(g_x1 + (size_t)(row0 + rr + 8) * 128 + c0);
        float2 y0; y0.x = d[t][0] + bb.x + r0v.x; y0.y = d[t][1] + bb.y + r0v.y;
        float2 y1; y1.x = d[t][2] + bb.x + r1v.x; y1.y = d[t][3] + bb.y + r1v.y;
        *(float2 *)(ys + rr * 128 + c0) = y0;
        *(float2 *)(ys + (rr + 8) * 128 + c0) = y1;
    }
    __syncthreads();

    // LN2: 8 warps x 8 rows
    for (int jj = 0; jj < 8; ++jj) {
        int rr = wid * 8 + jj;
        float z[4];
#pragma unroll
        for (int j = 0; j < 4; ++j) z[j] = ys[rr * 128 + lane + 32 * j];
        float s2 = z[0] + z[1] + z[2] + z[3];
#pragma unroll
        for (int o = 16; o > 0; o >>= 1) s2 += __shfl_xor_sync(0xffffffffu, s2, o);
        float mu = s2 * (1.0f / 128.0f);
        float v = 0.f;
#pragma unroll
        for (int j = 0; j < 4; ++j) { float dd = z[j] - mu; v += dd * dd; }
#pragma unroll
        for (int o = 16; o > 0; o >>= 1) v += __shfl_xor_sync(0xffffffffu, v, o);
        float rstd = rsqrtf(v * (1.0f / 128.0f) + 1e-5f);
#pragma unroll
        for (int j = 0; j < 4; ++j) {
            int c = lane + 32 * j;
            g_out2[(size_t)(row0 + rr) * 128 + c] = (z[j] - mu) * rstd * ln2g[c] + ln2b[c];
        }
    }
}

// ----- out[b,c,t] = sum_n out2[((b*32+n)*256+t)*128 + c]; block=(t,b) -------
__global__ void reduce_kernel(float *__restrict__ out) {
    int t = blockIdx.x & 255, b = blockIdx.x >> 8;
    int c = threadIdx.x;
    float s = 0.f;
    const float *base = g_out2 + (size_t)b * 32 * 256 * 128 + t * 128 + c;
#pragma unroll 8
    for (int n = 0; n < 32; ++n) s += base[n * 256 * 128];
    out[((b * 128 + c) << 8) + t] = s;
}

extern "C" void kernel_launch(void* const* d_in, const int* in_sizes, int n_in,
                              void* d_out, int out_size) {
    const float *x     = (const float *)d_in[0];
    const float *mlp_w = (const float *)d_in[1];
    const float *mlp_b = (const float *)d_in[2];
    const float *wq = (const float *)d_in[3],  *bq = (const float *)d_in[4];
    const float *wk = (const float *)d_in[5],  *bk = (const float *)d_in[6];
    const float *wv = (const float *)d_in[7],  *bv = (const float *)d_in[8];
    const float *wo = (const float *)d_in[9],  *bo = (const float *)d_in[10];
    const float *w1 = (const float *)d_in[11], *b1 = (const float *)d_in[12];
    const float *w2 = (const float *)d_in[13], *b2 = (const float *)d_in[14];
    const float *ln1g = (const float *)d_in[15], *ln1b = (const float *)d_in[16];
    const float *ln2g = (const float *)d_in[17], *ln2b = (const float *)d_in[18];
    float *out = (float *)d_out;

    cudaFuncSetAttribute(ffn_kernel, cudaFuncAttributeMaxDynamicSharedMemorySize, FFN_SMEM);

    prep_consts<<<1, 128>>>(mlp_w, mlp_b, wq, bq, wk, bk, wv, bv, wo, bo);
    idx_kernel<<<9, 256>>>();
    convert_w<<<256, 256>>>(w1, w2);
    attn_kernel<<<128, 256>>>(x);
    ln1_kernel<<<TOK / 8, 256>>>(x, mlp_w, mlp_b, ln1g, ln1b);
    ffn_kernel<<<TOK / 64, 256, FFN_SMEM>>>(b1, b2, ln2g, ln2b);
    reduce_kernel<<<4 * 256, 128>>>(out);
}

// round 4
// speedup vs baseline: 3.0861x; 1.0167x over previous
#include <cuda_runtime.h>
#include <cuda_bf16.h>
#include <math.h>

// InformerLayer: b=4,N=32,T=256 -> B=128 seqs, L=256, C=128, H=8, E=16, DFF=512, u=k=18
#define TOK 32768
#define UK  18

__device__ float g_Aq[128], g_Bq[128], g_Ak[128], g_Bk[128], g_Av[128], g_Bv[128];
__device__ float g_c1[8], g_c2[8], g_c3[8], g_c4[8];
__device__ float g_Po[8 * 128], g_Co[128];
__device__ int   g_idx[256 * UK];
__device__ float g_x1[TOK * 128];
__device__ unsigned g_x1bf[TOK * 64];     // bf16x2 x1, row-major [row][64]
__device__ float g_out2[TOK * 128];
// weights in mma-fragment order: uint4 per (n-block, k-group, lane)
__device__ unsigned g_w1f[64 * 4 * 32 * 4];    // [nb][g][lane][4]
__device__ unsigned g_w2f[16 * 16 * 32 * 4];   // [nb][g][lane][4]

static __device__ __forceinline__ unsigned packbf(float a, float b) {
    __nv_bfloat162 t = __floats2bfloat162_rn(a, b);
    return *reinterpret_cast<unsigned *>(&t);
}

__device__ __forceinline__ void mma16816(float &d0, float &d1, float &d2, float &d3,
                                         unsigned a0, unsigned a1, unsigned a2, unsigned a3,
                                         unsigned b0, unsigned b1) {
    asm volatile("mma.sync.aligned.m16n8k16.row.col.f32.bf16.bf16.f32 "
                 "{%0,%1,%2,%3},{%4,%5,%6,%7},{%8,%9},{%0,%1,%2,%3};"
                 : "+f"(d0), "+f"(d1), "+f"(d2), "+f"(d3)
                 : "r"(a0), "r"(a1), "r"(a2), "r"(a3), "r"(b0), "r"(b1));
}

// ------------------------------- Threefry ---------------------------------
__device__ __forceinline__ void tf_r(unsigned &x0, unsigned &x1, int r) {
    x0 += x1; x1 = (x1 << r) | (x1 >> (32 - r)); x1 ^= x0;
}
__device__ void threefry2x32(unsigned k0, unsigned k1, unsigned c0, unsigned c1,
                             unsigned &o0, unsigned &o1) {
    unsigned ks2 = k0 ^ k1 ^ 0x1BD11BDAu;
    unsigned x0 = c0 + k0, x1 = c1 + k1;
    tf_r(x0,x1,13); tf_r(x0,x1,15); tf_r(x0,x1,26); tf_r(x0,x1,6);
    x0 += k1;  x1 += ks2 + 1u;
    tf_r(x0,x1,17); tf_r(x0,x1,29); tf_r(x0,x1,16); tf_r(x0,x1,24);
    x0 += ks2; x1 += k0 + 2u;
    tf_r(x0,x1,13); tf_r(x0,x1,15); tf_r(x0,x1,26); tf_r(x0,x1,6);
    x0 += k0;  x1 += k1 + 3u;
    tf_r(x0,x1,17); tf_r(x0,x1,29); tf_r(x0,x1,16); tf_r(x0,x1,24);
    x0 += k1;  x1 += ks2 + 4u;
    tf_r(x0,x1,13); tf_r(x0,x1,15); tf_r(x0,x1,26); tf_r(x0,x1,6);
    x0 += ks2; x1 += k0 + 5u;
    o0 = x0; o1 = x1;
}

// --------------- fused setup: consts / threefry idx / weight frags ----------
__global__ void setup_kernel(const float *__restrict__ mlp_w, const float *__restrict__ mlp_b,
                             const float *__restrict__ wq, const float *__restrict__ bq,
                             const float *__restrict__ wk, const float *__restrict__ bk,
                             const float *__restrict__ wv, const float *__restrict__ bv,
                             const float *__restrict__ wo, const float *__restrict__ bo,
                             const float *__restrict__ w1, const float *__restrict__ w2) {
    int b = blockIdx.x, tid = threadIdx.x;
    if (b == 0) {
        int c = tid;
        if (c < 128) {
            float aq = 0.f, bq2 = 0.f, ak = 0.f, bk2 = 0.f, av = 0.f, bv2 = 0.f;
            for (int j = 0; j < 128; ++j) {
                float mw = mlp_w[j], mb = mlp_b[j];
                float q = wq[c * 128 + j], k = wk[c * 128 + j], v = wv[c * 128 + j];
                aq = fmaf(mw, q, aq); bq2 = fmaf(mb, q, bq2);
                ak = fmaf(mw, k, ak); bk2 = fmaf(mb, k, bk2);
                av = fmaf(mw, v, av); bv2 = fmaf(mb, v, bv2);
            }
            g_Aq[c] = aq; g_Bq[c] = bq2 + bq[c];
            g_Ak[c] = ak; g_Bk[c] = bk2 + bk[c];
            g_Av[c] = av; g_Bv[c] = bv2 + bv[c];
        }
        __syncthreads();
        if (tid < 8) {
            int h = tid;
            float c1 = 0.f, c2 = 0.f, c3 = 0.f, c4 = 0.f;
            for (int e = 0; e < 16; ++e) {
                int i = h * 16 + e;
                c1 += g_Aq[i] * g_Ak[i];
                c2 += g_Aq[i] * g_Bk[i];
                c3 += g_Bq[i] * g_Ak[i];
                c4 += g_Bq[i] * g_Bk[i];
            }
            g_c1[h] = c1; g_c2[h] = c2; g_c3[h] = c3; g_c4[h] = c4;
        }
        if (tid < 128) {
            int c = tid;
            float co = bo[c];
            for (int j = 0; j < 128; ++j) co = fmaf(g_Bv[j], wo[c * 128 + j], co);
            g_Co[c] = co;
            for (int h = 0; h < 8; ++h) {
                float p = 0.f;
                for (int e = 0; e < 16; ++e)
                    p = fmaf(g_Av[h * 16 + e], wo[c * 128 + h * 16 + e], p);
                g_Po[h * 128 + c] = p;
            }
        }
    } else if (b <= 9) {
        int i = (b - 1) * 256 + tid;   // 0..2303
        unsigned a0, a1, b0, b1;
        threefry2x32(0u, 42u, 0u, 2u, a0, a1);
        threefry2x32(0u, 42u, 1u, 3u, b0, b1);
        unsigned y0, y1;
        threefry2x32(a1, b1, (unsigned)i, (unsigned)(2304 + i), y0, y1);
        g_idx[i]        = (int)(y0 & 255u);
        g_idx[2304 + i] = (int)(y1 & 255u);
    } else {
        int j = (b - 10) * 256 + tid;  // 0..65535
        if (j < 32768) {               // w1 frags: [nb 64][g 4][lane 32][4]
            int jj = j & 3, u4 = j >> 2;
            int lane = u4 & 31, g = (u4 >> 5) & 3, nb = u4 >> 7;
            int n = nb * 8 + (lane >> 2);
            int kp = g * 16 + (lane & 3) + jj * 4;
            g_w1f[j] = packbf(w1[n * 128 + 2 * kp], w1[n * 128 + 2 * kp + 1]);
        } else {                       // w2 frags: [nb 16][g 16][lane 32][4]
            int j2 = j - 32768;
            int jj = j2 & 3, u4 = j2 >> 2;
            int lane = u4 & 31, g = (u4 >> 5) & 15, nb = u4 >> 9;
            int n = nb * 8 + (lane >> 2);
            int kp = g * 16 + (lane & 3) + jj * 4;
            g_w2f[j2] = packbf(w2[n * 512 + 2 * kp], w2[n * 512 + 2 * kp + 1]);
        }
    }
}

// ------- fused attention (M, reg top-18, softmax) + LN1; block = seq --------
__global__ void __launch_bounds__(256)
attn_ln1_kernel(const float *__restrict__ x,
                const float *__restrict__ mlp_w, const float *__restrict__ mlp_b,
                const float *__restrict__ ln1g, const float *__restrict__ ln1b) {
    __shared__ float xs[256];
    __shared__ float al[256 * 8];     // alpha[t][h]
    __shared__ int   midx[8][UK];
    int tid = threadIdx.x, lane = tid & 31, h = tid >> 5;
    int seq = blockIdx.x;
    xs[tid] = x[seq * 256 + tid];
    __syncthreads();

    float s = 0.f;
#pragma unroll
    for (int k = 0; k < 8; ++k) s += xs[lane + 32 * k];
#pragma unroll
    for (int o = 16; o > 0; o >>= 1) s += __shfl_xor_sync(0xffffffffu, s, o);
    float xbar = s * (1.0f / 256.0f);

    float c1 = g_c1[h], c2 = g_c2[h], c3 = g_c3[h], c4 = g_c4[h];
    float Mreg[8];
#pragma unroll
    for (int k = 0; k < 8; ++k) {
        int t = lane + 32 * k;
        float xl = xs[t];
        float mx = -3.4e38f, sm = 0.f;
#pragma unroll
        for (int j = 0; j < UK; ++j) {
            float xv = xs[g_idx[t * UK + j]];
            float sc = c1 * xl * xv + c2 * xl + c3 * xv + c4;
            mx = fmaxf(mx, sc);
            sm += sc;
        }
        Mreg[k] = mx - sm * (1.0f / 256.0f);
        al[t * 8 + h] = xbar;
    }

    // register-resident serial top-18 (ties -> lowest index)
    for (int it = 0; it < UK; ++it) {
        float bv = -3.4e38f; int bi = 256;
#pragma unroll
        for (int k = 0; k < 8; ++k) {
            int t = lane + 32 * k;
            if (Mreg[k] > bv) { bv = Mreg[k]; bi = t; }
        }
#pragma unroll
        for (int o = 16; o > 0; o >>= 1) {
            float ov = __shfl_xor_sync(0xffffffffu, bv, o);
            int   oi = __shfl_xor_sync(0xffffffffu, bi, o);
            if (ov > bv || (ov == bv && oi < bi)) { bv = ov; bi = oi; }
        }
#pragma unroll
        for (int k = 0; k < 8; ++k)
            if ((bi >> 5) == k && (bi & 31) == lane) Mreg[k] = -3.4e38f;
        if (lane == 0) midx[h][it] = bi;
    }
    __syncthreads();

    // 144 softmax rows across 8 warps
    for (int p = h; p < 8 * UK; p += 8) {
        int h2 = p / UK, it = p % UK;
        int m = midx[h2][it];
        float d1 = g_c1[h2], d2 = g_c2[h2], d3 = g_c3[h2], d4 = g_c4[h2];
        float xm = xs[m];
        float sc[8], rmax = -3.4e38f;
#pragma unroll
        for (int k = 0; k < 8; ++k) {
            float xv = xs[lane + 32 * k];
            sc[k] = 0.25f * (d1 * xm * xv + d2 * xm + d3 * xv + d4);
            rmax = fmaxf(rmax, sc[k]);
        }
#pragma unroll
        for (int o = 16; o > 0; o >>= 1) rmax = fmaxf(rmax, __shfl_xor_sync(0xffffffffu, rmax, o));
        float Z = 0.f, S = 0.f;
#pragma unroll
        for (int k = 0; k < 8; ++k) {
            float e = __expf(sc[k] - rmax);
            Z += e;
            S += e * xs[lane + 32 * k];
        }
#pragma unroll
        for (int o = 16; o > 0; o >>= 1) {
            Z += __shfl_xor_sync(0xffffffffu, Z, o);
            S += __shfl_xor_sync(0xffffffffu, S, o);
        }
        if (lane == 0) al[m * 8 + h2] = S / Z;
    }
    __syncthreads();

    // LN1: lane owns cols 4L..4L+3; warp h owns rows 32h..32h+31
    float po[8][4], mw[4], mb[4], co[4], lg[4], lb[4];
    {
        int c0 = lane * 4;
        *(float4 *)mw = *(const float4 *)(mlp_w + c0);
        *(float4 *)mb = *(const float4 *)(mlp_b + c0);
        *(float4 *)co = *(const float4 *)(g_Co + c0);
        *(float4 *)lg = *(const float4 *)(ln1g + c0);
        *(float4 *)lb = *(const float4 *)(ln1b + c0);
#pragma unroll
        for (int hh = 0; hh < 8; ++hh)
            *(float4 *)po[hh] = *(const float4 *)(g_Po + hh * 128 + c0);
    }
    for (int rr = 0; rr < 32; ++rr) {
        int row = h * 32 + rr;
        float xv = xs[row];
        float a[8];
#pragma unroll
        for (int hh = 0; hh < 8; ++hh) a[hh] = al[row * 8 + hh];
        float z[4];
#pragma unroll
        for (int j = 0; j < 4; ++j) {
            float zc = fmaf(xv, mw[j], mb[j]) + co[j];
#pragma unroll
            for (int hh = 0; hh < 8; ++hh) zc = fmaf(a[hh], po[hh][j], zc);
            z[j] = zc;
        }
        float s2 = z[0] + z[1] + z[2] + z[3];
#pragma unroll
        for (int o = 16; o > 0; o >>= 1) s2 += __shfl_xor_sync(0xffffffffu, s2, o);
        float mu = s2 * (1.0f / 128.0f);
        float v = 0.f;
#pragma unroll
        for (int j = 0; j < 4; ++j) { float d = z[j] - mu; v += d * d; }
#pragma unroll
        for (int o = 16; o > 0; o >>= 1) v += __shfl_xor_sync(0xffffffffu, v, o);
        float rstd = rsqrtf(v * (1.0f / 128.0f) + 1e-5f);
        size_t grow = (size_t)seq * 256 + row;
        float out[4];
#pragma unroll
        for (int j = 0; j < 4; ++j) out[j] = (z[j] - mu) * rstd * lg[j] + lb[j];
        *(float4 *)(g_x1 + grow * 128 + lane * 4) = *(float4 *)out;
        uint2 pk; pk.x = packbf(out[0], out[1]); pk.y = packbf(out[2], out[3]);
        *(uint2 *)(g_x1bf + grow * 64 + lane * 2) = pk;
    }
}

// ---------- FFN + residual + LN2; weights via fragment LDG.128 -------------
#define TS_U32 (64 * 260)
#define YS_STRIDE 132
#define FFN_SMEM (TS_U32 * 4)

__global__ void __launch_bounds__(256)
ffn_kernel(const float *__restrict__ b1, const float *__restrict__ b2,
           const float *__restrict__ ln2g, const float *__restrict__ ln2b) {
    extern __shared__ unsigned ts[];   // [64][260] bf16x2; later ys fp32 [64][132]
    int tid = threadIdx.x;
    int wid = tid >> 5, lane = tid & 31;
    int row0 = blockIdx.x * 64;
    int r = lane >> 2, q = lane & 3;
    int ms = wid & 3, nh = wid >> 2;

    // GEMM1: X[64,128] @ w1^T -> relu -> ts bf16 [64][512]
    {
        unsigned a[8][4];
        const unsigned *A = g_x1bf + (size_t)(row0 + ms * 16) * 64;
#pragma unroll
        for (int kk = 0; kk < 8; ++kk) {
            a[kk][0] = A[r * 64 + kk * 8 + q];
            a[kk][1] = A[(r + 8) * 64 + kk * 8 + q];
            a[kk][2] = A[r * 64 + kk * 8 + q + 4];
            a[kk][3] = A[(r + 8) * 64 + kk * 8 + q + 4];
        }
        const uint4 *W1 = (const uint4 *)g_w1f;
#pragma unroll 4
        for (int t = 0; t < 32; ++t) {
            int nb = nh * 32 + t;
            float d0 = 0.f, d1 = 0.f, d2 = 0.f, d3 = 0.f;
#pragma unroll
            for (int g = 0; g < 4; ++g) {
                uint4 B = W1[(nb * 4 + g) * 32 + lane];
                mma16816(d0, d1, d2, d3, a[2*g][0], a[2*g][1], a[2*g][2], a[2*g][3], B.x, B.y);
                mma16816(d0, d1, d2, d3, a[2*g+1][0], a[2*g+1][1], a[2*g+1][2], a[2*g+1][3], B.z, B.w);
            }
            int n0 = nb * 8, c0 = n0 + q * 2;
            float2 bb = *(const float2 *)(b1 + c0);
            d0 = fmaxf(d0 + bb.x, 0.f); d1 = fmaxf(d1 + bb.y, 0.f);
            d2 = fmaxf(d2 + bb.x, 0.f); d3 = fmaxf(d3 + bb.y, 0.f);
            ts[(ms * 16 + r) * 260 + nb * 4 + q]     = packbf(d0, d1);
            ts[(ms * 16 + r + 8) * 260 + nb * 4 + q] = packbf(d2, d3);
        }
    }
    __syncthreads();

    // GEMM2: T[64,512] @ w2^T -> d[8][4] (warp covers n-half of 64)
    float d[8][4];
#pragma unroll
    for (int t = 0; t < 8; ++t) { d[t][0]=0.f; d[t][1]=0.f; d[t][2]=0.f; d[t][3]=0.f; }
    {
        const unsigned *At = ts + (ms * 16) * 260;
        const uint4 *W2 = (const uint4 *)g_w2f;
#pragma unroll 2
        for (int g = 0; g < 16; ++g) {
            unsigned a0[4], a1[4];
            a0[0] = At[r * 260 + g * 16 + q];
            a0[1] = At[(r + 8) * 260 + g * 16 + q];
            a0[2] = At[r * 260 + g * 16 + q + 4];
            a0[3] = At[(r + 8) * 260 + g * 16 + q + 4];
            a1[0] = At[r * 260 + g * 16 + q + 8];
            a1[1] = At[(r + 8) * 260 + g * 16 + q + 8];
            a1[2] = At[r * 260 + g * 16 + q + 12];
            a1[3] = At[(r + 8) * 260 + g * 16 + q + 12];
#pragma unroll
            for (int t = 0; t < 8; ++t) {
                uint4 B = W2[(((nh * 8 + t) * 16) + g) * 32 + lane];
                mma16816(d[t][0], d[t][1], d[t][2], d[t][3],
                         a0[0], a0[1], a0[2], a0[3], B.x, B.y);
                mma16816(d[t][0], d[t][1], d[t][2], d[t][3],
                         a1[0], a1[1], a1[2], a1[3], B.z, B.w);
            }
        }
    }
    __syncthreads();

    // ys = y + b2 + residual (reuse ts as fp32 [64][132])
    float *ys = (float *)ts;
#pragma unroll
    for (int t = 0; t < 8; ++t) {
        int n0 = (nh * 8 + t) * 8, c0 = n0 + q * 2;
        float2 bb = *(const float2 *)(b2 + c0);
        int rr = ms * 16 + r;
        float2 r0v = *(const float2 *)(g_x1 + (size_t)(row0 + rr) * 128 + c0);
        float2 r1v = *(const float2 *)(g_x1 + (size_t)(row0 + rr + 8) * 128 + c0);
        float2 y0; y0.x = d[t][0] + bb.x + r0v.x; y0.y = d[t][1] + bb.y + r0v.y;
        float2 y1; y1.x = d[t][2] + bb.x + r1v.x; y1.y = d[t][3] + bb.y + r1v.y;
        *(float2 *)(ys + rr * YS_STRIDE + c0) = y0;
        *(float2 *)(ys + (rr + 8) * YS_STRIDE + c0) = y1;
    }
    __syncthreads();

    // LN2: 8 warps x 8 rows
#pragma unroll
    for (int jj = 0; jj < 8; ++jj) {
        int rr = wid * 8 + jj;
        float z[4];
#pragma unroll
        for (int j = 0; j < 4; ++j) z[j] = ys[rr * YS_STRIDE + lane + 32 * j];
        float s2 = z[0] + z[1] + z[2] + z[3];
#pragma unroll
        for (int o = 16; o > 0; o >>= 1) s2 += __shfl_xor_sync(0xffffffffu, s2, o);
        float mu = s2 * (1.0f / 128.0f);
        float v = 0.f;
#pragma unroll
        for (int j = 0; j < 4; ++j) { float dd = z[j] - mu; v += dd * dd; }
#pragma unroll
        for (int o = 16; o > 0; o >>= 1) v += __shfl_xor_sync(0xffffffffu, v, o);
        float rstd = rsqrtf(v * (1.0f / 128.0f) + 1e-5f);
#pragma unroll
        for (int j = 0; j < 4; ++j) {
            int c = lane + 32 * j;
            g_out2[(size_t)(row0 + rr) * 128 + c] = (z[j] - mu) * rstd * ln2g[c] + ln2b[c];
        }
    }
}

// ----- out[b,c,t] = sum_n out2[((b*32+n)*256+t)*128 + c]; block=(t,b) -------
__global__ void reduce_kernel(float *__restrict__ out) {
    int t = blockIdx.x & 255, b = blockIdx.x >> 8;
    int c = threadIdx.x;
    float s = 0.f;
    const float *base = g_out2 + (size_t)b * 32 * 256 * 128 + t * 128 + c;
#pragma unroll 8
    for (int n = 0; n < 32; ++n) s += base[n * 256 * 128];
    out[((b * 128 + c) << 8) + t] = s;
}

extern "C" void kernel_launch(void* const* d_in, const int* in_sizes, int n_in,
                              void* d_out, int out_size) {
    const float *x     = (const float *)d_in[0];
    const float *mlp_w = (const float *)d_in[1];
    const float *mlp_b = (const float *)d_in[2];
    const float *wq = (const float *)d_in[3],  *bq = (const float *)d_in[4];
    const float *wk = (const float *)d_in[5],  *bk = (const float *)d_in[6];
    const float *wv = (const float *)d_in[7],  *bv = (const float *)d_in[8];
    const float *wo = (const float *)d_in[9],  *bo = (const float *)d_in[10];
    const float *w1 = (const float *)d_in[11], *b1 = (const float *)d_in[12];
    const float *w2 = (const float *)d_in[13], *b2 = (const float *)d_in[14];
    const float *ln1g = (const float *)d_in[15], *ln1b = (const float *)d_in[16];
    const float *ln2g = (const float *)d_in[17], *ln2b = (const float *)d_in[18];
    float *out = (float *)d_out;

    cudaFuncSetAttribute(ffn_kernel, cudaFuncAttributeMaxDynamicSharedMemorySize, FFN_SMEM);

    setup_kernel<<<266, 256>>>(mlp_w, mlp_b, wq, bq, wk, bk, wv, bv, wo, bo, w1, w2);
    attn_ln1_kernel<<<128, 256>>>(x, mlp_w, mlp_b, ln1g, ln1b);
    ffn_kernel<<<TOK / 64, 256, FFN_SMEM>>>(b1, b2, ln2g, ln2b);
    reduce_kernel<<<4 * 256, 128>>>(out);
}

// round 6
// speedup vs baseline: 3.3491x; 1.0852x over previous
#include <cuda_runtime.h>
#include <cuda_bf16.h>
#include <math.h>
#include <cstdint>

// InformerLayer: b=4,N=32,T=256 -> B=128 seqs, L=256, C=128, H=8, E=16, DFF=512, u=k=18
#define TOK 32768
#define UK  18

__device__ float g_Aq[128], g_Bq[128], g_Ak[128], g_Bk[128], g_Av[128], g_Bv[128];
__device__ float g_c1[8], g_c2[8], g_c3[8], g_c4[8];
__device__ float g_Po[8 * 128], g_Co[128];
__device__ int   g_idx[256 * UK];
__device__ float g_zm[10];           // mean of z-basis rows
__device__ float g_G[100];           // Gram matrix of z-basis rows (/128)
__device__ float g_V[12 * 128];      // x1 = u @ V
__device__ float g_u[TOK * 12];      // per-row coefficients (fp32)
__device__ unsigned g_ubf[TOK * 8];  // u padded to 16, bf16x2
__device__ float g_out2[TOK * 128];
__device__ uint2 g_w1f2[64 * 32];            // W1' B-frags: [ntile][lane]
__device__ unsigned g_w2f[16 * 16 * 32 * 4]; // w2 B-frags: [nb][g][lane][4]

static __device__ __forceinline__ unsigned packbf(float a, float b) {
    __nv_bfloat162 t = __floats2bfloat162_rn(a, b);
    return *reinterpret_cast<unsigned *>(&t);
}

__device__ __forceinline__ void mma16816(float &d0, float &d1, float &d2, float &d3,
                                         unsigned a0, unsigned a1, unsigned a2, unsigned a3,
                                         unsigned b0, unsigned b1) {
    asm volatile("mma.sync.aligned.m16n8k16.row.col.f32.bf16.bf16.f32 "
                 "{%0,%1,%2,%3},{%4,%5,%6,%7},{%8,%9},{%0,%1,%2,%3};"
                 : "+f"(d0), "+f"(d1), "+f"(d2), "+f"(d3)
                 : "r"(a0), "r"(a1), "r"(a2), "r"(a3), "r"(b0), "r"(b1));
}

// ------------------------------- Threefry ---------------------------------
__device__ __forceinline__ void tf_r(unsigned &x0, unsigned &x1, int r) {
    x0 += x1; x1 = (x1 << r) | (x1 >> (32 - r)); x1 ^= x0;
}
__device__ void threefry2x32(unsigned k0, unsigned k1, unsigned c0, unsigned c1,
                             unsigned &o0, unsigned &o1) {
    unsigned ks2 = k0 ^ k1 ^ 0x1BD11BDAu;
    unsigned x0 = c0 + k0, x1 = c1 + k1;
    tf_r(x0,x1,13); tf_r(x0,x1,15); tf_r(x0,x1,26); tf_r(x0,x1,6);
    x0 += k1;  x1 += ks2 + 1u;
    tf_r(x0,x1,17); tf_r(x0,x1,29); tf_r(x0,x1,16); tf_r(x0,x1,24);
    x0 += ks2; x1 += k0 + 2u;
    tf_r(x0,x1,13); tf_r(x0,x1,15); tf_r(x0,x1,26); tf_r(x0,x1,6);
    x0 += k0;  x1 += k1 + 3u;
    tf_r(x0,x1,17); tf_r(x0,x1,29); tf_r(x0,x1,16); tf_r(x0,x1,24);
    x0 += k1;  x1 += ks2 + 4u;
    tf_r(x0,x1,13); tf_r(x0,x1,15); tf_r(x0,x1,26); tf_r(x0,x1,6);
    x0 += ks2; x1 += k0 + 5u;
    o0 = x0; o1 = x1;
}

// ---- setup1: consts + z-basis stats (m, G) + V + idx + w2 frags ------------
__global__ void setup1_kernel(const float *__restrict__ mlp_w, const float *__restrict__ mlp_b,
                              const float *__restrict__ wq, const float *__restrict__ bq,
                              const float *__restrict__ wk, const float *__restrict__ bk,
                              const float *__restrict__ wv, const float *__restrict__ bv,
                              const float *__restrict__ wo, const float *__restrict__ bo,
                              const float *__restrict__ ln1g, const float *__restrict__ ln1b,
                              const float *__restrict__ w2) {
    int b = blockIdx.x, tid = threadIdx.x;
    if (b == 0) {
        __shared__ float sB[10][128];   // z-basis rows
        int c = tid;
        if (c < 128) {
            float aq = 0.f, bq2 = 0.f, ak = 0.f, bk2 = 0.f, av = 0.f, bv2 = 0.f;
            for (int j = 0; j < 128; ++j) {
                float mw = mlp_w[j], mb = mlp_b[j];
                float q = wq[c * 128 + j], k = wk[c * 128 + j], v = wv[c * 128 + j];
                aq = fmaf(mw, q, aq); bq2 = fmaf(mb, q, bq2);
                ak = fmaf(mw, k, ak); bk2 = fmaf(mb, k, bk2);
                av = fmaf(mw, v, av); bv2 = fmaf(mb, v, bv2);
            }
            g_Aq[c] = aq; g_Bq[c] = bq2 + bq[c];
            g_Ak[c] = ak; g_Bk[c] = bk2 + bk[c];
            g_Av[c] = av; g_Bv[c] = bv2 + bv[c];
        }
        __syncthreads();
        if (tid < 8) {
            int h = tid;
            float c1 = 0.f, c2 = 0.f, c3 = 0.f, c4 = 0.f;
            for (int e = 0; e < 16; ++e) {
                int i = h * 16 + e;
                c1 += g_Aq[i] * g_Ak[i];
                c2 += g_Aq[i] * g_Bk[i];
                c3 += g_Bq[i] * g_Ak[i];
                c4 += g_Bq[i] * g_Bk[i];
            }
            g_c1[h] = c1; g_c2[h] = c2; g_c3[h] = c3; g_c4[h] = c4;
        }
        if (c < 128) {
            float co = bo[c];
            for (int j = 0; j < 128; ++j) co = fmaf(g_Bv[j], wo[c * 128 + j], co);
            g_Co[c] = co;
            float po[8];
            for (int h = 0; h < 8; ++h) {
                float p = 0.f;
                for (int e = 0; e < 16; ++e)
                    p = fmaf(g_Av[h * 16 + e], wo[c * 128 + h * 16 + e], p);
                g_Po[h * 128 + c] = p;
                po[h] = p;
            }
            // z basis: [mw, Po_1..8, K] with K = mlp_b + Co
            float K = mlp_b[c] + co;
            sB[0][c] = mlp_w[c];
            for (int h = 0; h < 8; ++h) sB[1 + h][c] = po[h];
            sB[9][c] = K;
            // V rows: x1 = u @ V
            float g = ln1g[c];
            g_V[0 * 128 + c] = mlp_w[c] * g;
            for (int h = 0; h < 8; ++h) g_V[(1 + h) * 128 + c] = po[h] * g;
            g_V[9 * 128 + c]  = K * g;
            g_V[10 * 128 + c] = g;
            g_V[11 * 128 + c] = ln1b[c];
        }
        __syncthreads();
        if (tid < 100) {
            int i = tid / 10, j = tid % 10;
            float s = 0.f;
            for (int c2 = 0; c2 < 128; ++c2) s += sB[i][c2] * sB[j][c2];
            g_G[tid] = s * (1.0f / 128.0f);
        } else if (tid < 110) {
            int i = tid - 100;
            float s = 0.f;
            for (int c2 = 0; c2 < 128; ++c2) s += sB[i][c2];
            g_zm[i] = s * (1.0f / 128.0f);
        }
    } else if (b <= 9) {
        int i = (b - 1) * 256 + tid;   // 0..2303
        unsigned a0, a1, b0, b1;
        threefry2x32(0u, 42u, 0u, 2u, a0, a1);
        threefry2x32(0u, 42u, 1u, 3u, b0, b1);
        unsigned y0, y1;
        threefry2x32(a1, b1, (unsigned)i, (unsigned)(2304 + i), y0, y1);
        g_idx[i]        = (int)(y0 & 255u);
        g_idx[2304 + i] = (int)(y1 & 255u);
    } else {
        int j2 = (b - 10) * 256 + tid; // 0..32767: w2 frags [nb16][g16][lane32][4]
        int jj = j2 & 3, u4 = j2 >> 2;
        int lane = u4 & 31, g = (u4 >> 5) & 15, nb = u4 >> 9;
        int n = nb * 8 + (lane >> 2);
        int kp = g * 16 + (lane & 3) + jj * 4;
        g_w2f[j2] = packbf(w2[n * 512 + 2 * kp], w2[n * 512 + 2 * kp + 1]);
    }
}

// ---- setup2: W1' = V@w1^T (+b1 folded), stored as B-frags ------------------
__global__ void setup2_kernel(const float *__restrict__ w1, const float *__restrict__ b1) {
    int gid = blockIdx.x * 256 + threadIdx.x;   // 0..2047
    int lane = gid & 31, ntile = gid >> 5;
    int n = ntile * 8 + (lane >> 2), q = lane & 3;
    const float *w1n = w1 + n * 128;
    float d[4] = {0.f, 0.f, 0.f, 0.f};
    int ks[4] = {2 * q, 2 * q + 1, 2 * q + 8, 2 * q + 9};
#pragma unroll
    for (int m = 0; m < 4; ++m) {
        int k = ks[m];
        if (k < 12) {
            float s = 0.f;
            for (int c = 0; c < 128; ++c) s = fmaf(g_V[k * 128 + c], w1n[c], s);
            if (k == 11) s += b1[n];
            d[m] = s;
        }
    }
    g_w1f2[ntile * 32 + lane] = make_uint2(packbf(d[0], d[1]), packbf(d[2], d[3]));
}

// ------ attention (M, reg top-18, softmax) + closed-form LN1 stats ----------
__global__ void __launch_bounds__(256)
attn_kernel(const float *__restrict__ x) {
    __shared__ float xs[256];
    __shared__ float al[256 * 8];
    __shared__ int   midx[8][UK];
    __shared__ float zm[10], Gs[100];
    int tid = threadIdx.x, lane = tid & 31, h = tid >> 5;
    int seq = blockIdx.x;
    xs[tid] = x[seq * 256 + tid];
    if (tid < 100) Gs[tid] = g_G[tid];
    if (tid >= 100 && tid < 110) zm[tid - 100] = g_zm[tid - 100];
    __syncthreads();

    float s = 0.f;
#pragma unroll
    for (int k = 0; k < 8; ++k) s += xs[lane + 32 * k];
#pragma unroll
    for (int o = 16; o > 0; o >>= 1) s += __shfl_xor_sync(0xffffffffu, s, o);
    float xbar = s * (1.0f / 256.0f);

    float c1 = g_c1[h], c2 = g_c2[h], c3 = g_c3[h], c4 = g_c4[h];
    float Mreg[8];
#pragma unroll
    for (int k = 0; k < 8; ++k) {
        int t = lane + 32 * k;
        float xl = xs[t];
        float mx = -3.4e38f, sm = 0.f;
#pragma unroll
        for (int j = 0; j < UK; ++j) {
            float xv = xs[g_idx[t * UK + j]];
            float sc = c1 * xl * xv + c2 * xl + c3 * xv + c4;
            mx = fmaxf(mx, sc);
            sm += sc;
        }
        Mreg[k] = mx - sm * (1.0f / 256.0f);
        al[t * 8 + h] = xbar;
    }

    for (int it = 0; it < UK; ++it) {
        float bv = -3.4e38f; int bi = 256;
#pragma unroll
        for (int k = 0; k < 8; ++k) {
            int t = lane + 32 * k;
            if (Mreg[k] > bv) { bv = Mreg[k]; bi = t; }
        }
#pragma unroll
        for (int o = 16; o > 0; o >>= 1) {
            float ov = __shfl_xor_sync(0xffffffffu, bv, o);
            int   oi = __shfl_xor_sync(0xffffffffu, bi, o);
            if (ov > bv || (ov == bv && oi < bi)) { bv = ov; bi = oi; }
        }
#pragma unroll
        for (int k = 0; k < 8; ++k)
            if ((bi >> 5) == k && (bi & 31) == lane) Mreg[k] = -3.4e38f;
        if (lane == 0) midx[h][it] = bi;
    }
    __syncthreads();

    for (int p = h; p < 8 * UK; p += 8) {
        int h2 = p / UK, it = p % UK;
        int m = midx[h2][it];
        float d1 = g_c1[h2], d2 = g_c2[h2], d3 = g_c3[h2], d4 = g_c4[h2];
        float xm = xs[m];
        float sc[8], rmax = -3.4e38f;
#pragma unroll
        for (int k = 0; k < 8; ++k) {
            float xv = xs[lane + 32 * k];
            sc[k] = 0.25f * (d1 * xm * xv + d2 * xm + d3 * xv + d4);
            rmax = fmaxf(rmax, sc[k]);
        }
#pragma unroll
        for (int o = 16; o > 0; o >>= 1) rmax = fmaxf(rmax, __shfl_xor_sync(0xffffffffu, rmax, o));
        float Z = 0.f, S = 0.f;
#pragma unroll
        for (int k = 0; k < 8; ++k) {
            float e = __expf(sc[k] - rmax);
            Z += e;
            S += e * xs[lane + 32 * k];
        }
#pragma unroll
        for (int o = 16; o > 0; o >>= 1) {
            Z += __shfl_xor_sync(0xffffffffu, Z, o);
            S += __shfl_xor_sync(0xffffffffu, S, o);
        }
        if (lane == 0) al[m * 8 + h2] = S / Z;
    }
    __syncthreads();

    // closed-form LN1 stats for token tid: y = [x, a1..8, 1]
    float y[10];
    y[0] = xs[tid];
#pragma unroll
    for (int hh = 0; hh < 8; ++hh) y[1 + hh] = al[tid * 8 + hh];
    y[9] = 1.f;
    float mu = 0.f;
#pragma unroll
    for (int i = 0; i < 10; ++i) mu = fmaf(y[i], zm[i], mu);
    float q2 = 0.f;
#pragma unroll
    for (int i = 0; i < 10; ++i) {
        float acc = 0.f;
#pragma unroll
        for (int j = 0; j < 10; ++j) acc = fmaf(Gs[i * 10 + j], y[j], acc);
        q2 = fmaf(y[i], acc, q2);
    }
    float var = q2 - mu * mu;
    float r = rsqrtf(var + 1e-5f);
    float u[12];
#pragma unroll
    for (int i = 0; i < 9; ++i) u[i] = y[i] * r;   // [x*r, a1..8*r]
    u[9] = r; u[10] = -mu * r; u[11] = 1.f;

    size_t row = (size_t)seq * 256 + tid;
    float4 *up = (float4 *)(g_u + row * 12);
    up[0] = make_float4(u[0], u[1], u[2], u[3]);
    up[1] = make_float4(u[4], u[5], u[6], u[7]);
    up[2] = make_float4(u[8], u[9], u[10], u[11]);
    uint4 *ub = (uint4 *)(g_ubf + row * 8);
    ub[0] = make_uint4(packbf(u[0], u[1]), packbf(u[2], u[3]),
                       packbf(u[4], u[5]), packbf(u[6], u[7]));
    ub[1] = make_uint4(packbf(u[8], u[9]), packbf(u[10], u[11]), 0u, 0u);
}

// ---------- FFN + residual + LN2; GEMM1 K=16 (rank-12), GEMM2 K=512 --------
#define TS_U32 (64 * 260)
#define YS_STRIDE 132
#define OFF_US (TS_U32)              // 64*12 floats
#define OFF_VS (OFF_US + 64 * 12)    // 12*128 floats
#define OFF_B2 (OFF_VS + 12 * 128)
#define OFF_LG (OFF_B2 + 128)
#define OFF_LB (OFF_LG + 128)
#define FFN_SMEM ((OFF_LB + 128) * 4)

__global__ void __launch_bounds__(256)
ffn_kernel(const float *__restrict__ b2,
           const float *__restrict__ ln2g, const float *__restrict__ ln2b) {
    extern __shared__ unsigned ts[];   // [64][260] bf16x2; later ys fp32 [64][132]
    float *us  = (float *)(ts + OFF_US);
    float *Vs  = (float *)(ts + OFF_VS);
    float *b2s = (float *)(ts + OFF_B2);
    float *lgs = (float *)(ts + OFF_LG);
    float *lbs = (float *)(ts + OFF_LB);
    int tid = threadIdx.x;
    int wid = tid >> 5, lane = tid & 31;
    int row0 = blockIdx.x * 64;
    int r = lane >> 2, q = lane & 3;
    int ms = wid & 3, nh = wid >> 2;

    // stage u (64x12), V (12x128), b2/ln2 params
    for (int i = tid; i < 64 * 12; i += 256) us[i] = g_u[(size_t)row0 * 12 + i];
    for (int i = tid; i < 12 * 128; i += 256) Vs[i] = g_V[i];
    if (tid < 128) { b2s[tid] = b2[tid]; lgs[tid] = ln2g[tid]; lbs[tid] = ln2b[tid]; }

    // GEMM1: U[64,16] @ W1'^T -> relu -> ts bf16 [64][512]
    {
        unsigned a0, a1, a2, a3;
        const unsigned *U = g_ubf + (size_t)(row0 + ms * 16) * 8;
        a0 = U[r * 8 + q];
        a1 = U[(r + 8) * 8 + q];
        a2 = U[r * 8 + q + 4];
        a3 = U[(r + 8) * 8 + q + 4];
#pragma unroll 8
        for (int t = 0; t < 32; ++t) {
            int nb = nh * 32 + t;
            uint2 B = g_w1f2[nb * 32 + lane];
            float d0 = 0.f, d1 = 0.f, d2 = 0.f, d3 = 0.f;
            mma16816(d0, d1, d2, d3, a0, a1, a2, a3, B.x, B.y);
            d0 = fmaxf(d0, 0.f); d1 = fmaxf(d1, 0.f);
            d2 = fmaxf(d2, 0.f); d3 = fmaxf(d3, 0.f);
            ts[(ms * 16 + r) * 260 + nb * 4 + q]     = packbf(d0, d1);
            ts[(ms * 16 + r + 8) * 260 + nb * 4 + q] = packbf(d2, d3);
        }
    }
    __syncthreads();

    // GEMM2: T[64,512] @ w2^T -> d[8][4] (warp covers n-half of 64)
    float d[8][4];
#pragma unroll
    for (int t = 0; t < 8; ++t) { d[t][0]=0.f; d[t][1]=0.f; d[t][2]=0.f; d[t][3]=0.f; }
    {
        const unsigned *At = ts + (ms * 16) * 260;
        const uint4 *W2 = (const uint4 *)g_w2f;
#pragma unroll 2
        for (int g = 0; g < 16; ++g) {
            unsigned a0[4], a1[4];
            a0[0] = At[r * 260 + g * 16 + q];
            a0[1] = At[(r + 8) * 260 + g * 16 + q];
            a0[2] = At[r * 260 + g * 16 + q + 4];
            a0[3] = At[(r + 8) * 260 + g * 16 + q + 4];
            a1[0] = At[r * 260 + g * 16 + q + 8];
            a1[1] = At[(r + 8) * 260 + g * 16 + q + 8];
            a1[2] = At[r * 260 + g * 16 + q + 12];
            a1[3] = At[(r + 8) * 260 + g * 16 + q + 12];
#pragma unroll
            for (int t = 0; t < 8; ++t) {
                uint4 B = W2[(((nh * 8 + t) * 16) + g) * 32 + lane];
                mma16816(d[t][0], d[t][1], d[t][2], d[t][3],
                         a0[0], a0[1], a0[2], a0[3], B.x, B.y);
                mma16816(d[t][0], d[t][1], d[t][2], d[t][3],
                         a1[0], a1[1], a1[2], a1[3], B.z, B.w);
            }
        }
    }
    __syncthreads();

    // ys = y + b2 + residual (x1 reconstructed = u@V fp32); reuse ts as fp32
    float *ys = (float *)ts;
    {
        int rr = ms * 16 + r;
        float u0[12], u1[12];
#pragma unroll
        for (int k = 0; k < 12; ++k) { u0[k] = us[rr * 12 + k]; u1[k] = us[(rr + 8) * 12 + k]; }
#pragma unroll
        for (int t = 0; t < 8; ++t) {
            int c0 = (nh * 8 + t) * 8 + q * 2;
            float x00 = 0.f, x01 = 0.f, x10 = 0.f, x11 = 0.f;
#pragma unroll
            for (int k = 0; k < 12; ++k) {
                float v0 = Vs[k * 128 + c0], v1 = Vs[k * 128 + c0 + 1];
                x00 = fmaf(u0[k], v0, x00); x01 = fmaf(u0[k], v1, x01);
                x10 = fmaf(u1[k], v0, x10); x11 = fmaf(u1[k], v1, x11);
            }
            float bbx = b2s[c0], bby = b2s[c0 + 1];
            ys[rr * YS_STRIDE + c0]           = d[t][0] + bbx + x00;
            ys[rr * YS_STRIDE + c0 + 1]       = d[t][1] + bby + x01;
            ys[(rr + 8) * YS_STRIDE + c0]     = d[t][2] + bbx + x10;
            ys[(rr + 8) * YS_STRIDE + c0 + 1] = d[t][3] + bby + x11;
        }
    }
    __syncthreads();

    // LN2: 8 warps x 8 rows
#pragma unroll
    for (int jj = 0; jj < 8; ++jj) {
        int rr = wid * 8 + jj;
        float z[4];
#pragma unroll
        for (int j = 0; j < 4; ++j) z[j] = ys[rr * YS_STRIDE + lane + 32 * j];
        float s2 = z[0] + z[1] + z[2] + z[3];
#pragma unroll
        for (int o = 16; o > 0; o >>= 1) s2 += __shfl_xor_sync(0xffffffffu, s2, o);
        float mu = s2 * (1.0f / 128.0f);
        float v = 0.f;
#pragma unroll
        for (int j = 0; j < 4; ++j) { float dd = z[j] - mu; v += dd * dd; }
#pragma unroll
        for (int o = 16; o > 0; o >>= 1) v += __shfl_xor_sync(0xffffffffu, v, o);
        float rstd = rsqrtf(v * (1.0f / 128.0f) + 1e-5f);
#pragma unroll
        for (int j = 0; j < 4; ++j) {
            int c = lane + 32 * j;
            g_out2[(size_t)(row0 + rr) * 128 + c] = (z[j] - mu) * rstd * lgs[c] + lbs[c];
        }
    }
}

// ----- out[b,c,t] = sum_n out2[((b*32+n)*256+t)*128 + c] -------------------
__global__ void reduce_kernel(float *__restrict__ out) {
    __shared__ float sh[128];
    int t = blockIdx.x & 255, b = blockIdx.x >> 8;
    int c = threadIdx.x & 127, half = threadIdx.x >> 7;
    const float *base = g_out2 + (((size_t)(b * 32 + half * 16) * 256 + t) * 128) + c;
    float s = 0.f;
#pragma unroll
    for (int n = 0; n < 16; ++n) s += base[(size_t)n * 256 * 128];
    if (half) sh[c] = s;
    __syncthreads();
    if (!half) out[((b * 128 + c) << 8) + t] = s + sh[c];
}

extern "C" void kernel_launch(void* const* d_in, const int* in_sizes, int n_in,
                              void* d_out, int out_size) {
    const float *x     = (const float *)d_in[0];
    const float *mlp_w = (const float *)d_in[1];
    const float *mlp_b = (const float *)d_in[2];
    const float *wq = (const float *)d_in[3],  *bq = (const float *)d_in[4];
    const float *wk = (const float *)d_in[5],  *bk = (const float *)d_in[6];
    const float *wv = (const float *)d_in[7],  *bv = (const float *)d_in[8];
    const float *wo = (const float *)d_in[9],  *bo = (const float *)d_in[10];
    const float *w1 = (const float *)d_in[11], *b1 = (const float *)d_in[12];
    const float *w2 = (const float *)d_in[13], *b2 = (const float *)d_in[14];
    const float *ln1g = (const float *)d_in[15], *ln1b = (const float *)d_in[16];
    const float *ln2g = (const float *)d_in[17], *ln2b = (const float *)d_in[18];
    float *out = (float *)d_out;

    cudaFuncSetAttribute(ffn_kernel, cudaFuncAttributeMaxDynamicSharedMemorySize, FFN_SMEM);

    setup1_kernel<<<138, 256>>>(mlp_w, mlp_b, wq, bq, wk, bk, wv, bv, wo, bo,
                                ln1g, ln1b, w2);
    setup2_kernel<<<8, 256>>>(w1, b1);
    attn_kernel<<<128, 256>>>(x);
    ffn_kernel<<<TOK / 64, 256, FFN_SMEM>>>(b2, ln2g, ln2b);
    reduce_kernel<<<4 * 256, 256>>>(out);
}

// round 7
// speedup vs baseline: 3.5329x; 1.0549x over previous
#include <cuda_runtime.h>
#include <cuda_bf16.h>
#include <math.h>
#include <cstdint>

// InformerLayer: b=4,N=32,T=256 -> B=128 seqs, L=256, C=128, H=8, E=16, DFF=512, u=k=18
#define TOK 32768
#define UK  18

__device__ float g_Aq[128], g_Bq[128], g_Ak[128], g_Bk[128], g_Av[128], g_Bv[128];
__device__ float g_c1[8], g_c2[8], g_c3[8], g_c4[8];
__device__ float g_Po[8 * 128], g_Co[128];
__device__ int   g_idx[256 * UK];
__device__ float g_zm[10];           // mean of z-basis rows
__device__ float g_G[100];           // Gram matrix of z-basis rows (/128)
__device__ float g_V[12 * 128];      // x1 = u @ V
__device__ float g_u[TOK * 12];      // per-row coefficients (fp32)
__device__ unsigned g_ubf[TOK * 8];  // u padded to 16, bf16x2
__device__ float g_out2[TOK * 128];
__device__ uint2 g_w1f2[64 * 32];            // W1' B-frags: [ntile][lane]
__device__ unsigned g_w2f[16 * 16 * 32 * 4]; // w2 B-frags: [nb][g][lane][4]

static __device__ __forceinline__ unsigned packbf(float a, float b) {
    __nv_bfloat162 t = __floats2bfloat162_rn(a, b);
    return *reinterpret_cast<unsigned *>(&t);
}

__device__ __forceinline__ void mma16816(float &d0, float &d1, float &d2, float &d3,
                                         unsigned a0, unsigned a1, unsigned a2, unsigned a3,
                                         unsigned b0, unsigned b1) {
    asm volatile("mma.sync.aligned.m16n8k16.row.col.f32.bf16.bf16.f32 "
                 "{%0,%1,%2,%3},{%4,%5,%6,%7},{%8,%9},{%0,%1,%2,%3};"
                 : "+f"(d0), "+f"(d1), "+f"(d2), "+f"(d3)
                 : "r"(a0), "r"(a1), "r"(a2), "r"(a3), "r"(b0), "r"(b1));
}

#define LDMX4(r, addr) \
    asm volatile("ldmatrix.sync.aligned.m8n8.x4.shared.b16 {%0,%1,%2,%3}, [%4];" \
                 : "=r"((r)[0]), "=r"((r)[1]), "=r"((r)[2]), "=r"((r)[3]) : "r"(addr))

static __device__ __forceinline__ uint32_t smem_u32(const void *p) {
    uint32_t a;
    asm("{ .reg .u64 t; cvta.to.shared.u64 t, %1; cvt.u32.u64 %0, t; }" : "=r"(a) : "l"(p));
    return a;
}

// ------------------------------- Threefry ---------------------------------
__device__ __forceinline__ void tf_r(unsigned &x0, unsigned &x1, int r) {
    x0 += x1; x1 = (x1 << r) | (x1 >> (32 - r)); x1 ^= x0;
}
__device__ void threefry2x32(unsigned k0, unsigned k1, unsigned c0, unsigned c1,
                             unsigned &o0, unsigned &o1) {
    unsigned ks2 = k0 ^ k1 ^ 0x1BD11BDAu;
    unsigned x0 = c0 + k0, x1 = c1 + k1;
    tf_r(x0,x1,13); tf_r(x0,x1,15); tf_r(x0,x1,26); tf_r(x0,x1,6);
    x0 += k1;  x1 += ks2 + 1u;
    tf_r(x0,x1,17); tf_r(x0,x1,29); tf_r(x0,x1,16); tf_r(x0,x1,24);
    x0 += ks2; x1 += k0 + 2u;
    tf_r(x0,x1,13); tf_r(x0,x1,15); tf_r(x0,x1,26); tf_r(x0,x1,6);
    x0 += k0;  x1 += k1 + 3u;
    tf_r(x0,x1,17); tf_r(x0,x1,29); tf_r(x0,x1,16); tf_r(x0,x1,24);
    x0 += k1;  x1 += ks2 + 4u;
    tf_r(x0,x1,13); tf_r(x0,x1,15); tf_r(x0,x1,26); tf_r(x0,x1,6);
    x0 += ks2; x1 += k0 + 5u;
    o0 = x0; o1 = x1;
}

// ---- setup1: consts + z-basis stats (m, G) + V + idx + w2 frags ------------
__global__ void setup1_kernel(const float *__restrict__ mlp_w, const float *__restrict__ mlp_b,
                              const float *__restrict__ wq, const float *__restrict__ bq,
                              const float *__restrict__ wk, const float *__restrict__ bk,
                              const float *__restrict__ wv, const float *__restrict__ bv,
                              const float *__restrict__ wo, const float *__restrict__ bo,
                              const float *__restrict__ ln1g, const float *__restrict__ ln1b,
                              const float *__restrict__ w2) {
    int b = blockIdx.x, tid = threadIdx.x;
    if (b == 0) {
        __shared__ float sB[10][128];
        int c = tid;
        if (c < 128) {
            float aq = 0.f, bq2 = 0.f, ak = 0.f, bk2 = 0.f, av = 0.f, bv2 = 0.f;
            for (int j = 0; j < 128; ++j) {
                float mw = mlp_w[j], mb = mlp_b[j];
                float q = wq[c * 128 + j], k = wk[c * 128 + j], v = wv[c * 128 + j];
                aq = fmaf(mw, q, aq); bq2 = fmaf(mb, q, bq2);
                ak = fmaf(mw, k, ak); bk2 = fmaf(mb, k, bk2);
                av = fmaf(mw, v, av); bv2 = fmaf(mb, v, bv2);
            }
            g_Aq[c] = aq; g_Bq[c] = bq2 + bq[c];
            g_Ak[c] = ak; g_Bk[c] = bk2 + bk[c];
            g_Av[c] = av; g_Bv[c] = bv2 + bv[c];
        }
        __syncthreads();
        if (tid < 8) {
            int h = tid;
            float c1 = 0.f, c2 = 0.f, c3 = 0.f, c4 = 0.f;
            for (int e = 0; e < 16; ++e) {
                int i = h * 16 + e;
                c1 += g_Aq[i] * g_Ak[i];
                c2 += g_Aq[i] * g_Bk[i];
                c3 += g_Bq[i] * g_Ak[i];
                c4 += g_Bq[i] * g_Bk[i];
            }
            g_c1[h] = c1; g_c2[h] = c2; g_c3[h] = c3; g_c4[h] = c4;
        }
        if (c < 128) {
            float co = bo[c];
            for (int j = 0; j < 128; ++j) co = fmaf(g_Bv[j], wo[c * 128 + j], co);
            g_Co[c] = co;
            float po[8];
            for (int h = 0; h < 8; ++h) {
                float p = 0.f;
                for (int e = 0; e < 16; ++e)
                    p = fmaf(g_Av[h * 16 + e], wo[c * 128 + h * 16 + e], p);
                g_Po[h * 128 + c] = p;
                po[h] = p;
            }
            float K = mlp_b[c] + co;
            sB[0][c] = mlp_w[c];
            for (int h = 0; h < 8; ++h) sB[1 + h][c] = po[h];
            sB[9][c] = K;
            float g = ln1g[c];
            g_V[0 * 128 + c] = mlp_w[c] * g;
            for (int h = 0; h < 8; ++h) g_V[(1 + h) * 128 + c] = po[h] * g;
            g_V[9 * 128 + c]  = K * g;
            g_V[10 * 128 + c] = g;
            g_V[11 * 128 + c] = ln1b[c];
        }
        __syncthreads();
        if (tid < 100) {
            int i = tid / 10, j = tid % 10;
            float s = 0.f;
            for (int c2 = 0; c2 < 128; ++c2) s += sB[i][c2] * sB[j][c2];
            g_G[tid] = s * (1.0f / 128.0f);
        } else if (tid < 110) {
            int i = tid - 100;
            float s = 0.f;
            for (int c2 = 0; c2 < 128; ++c2) s += sB[i][c2];
            g_zm[i] = s * (1.0f / 128.0f);
        }
    } else if (b <= 9) {
        int i = (b - 1) * 256 + tid;
        unsigned a0, a1, b0, b1;
        threefry2x32(0u, 42u, 0u, 2u, a0, a1);
        threefry2x32(0u, 42u, 1u, 3u, b0, b1);
        unsigned y0, y1;
        threefry2x32(a1, b1, (unsigned)i, (unsigned)(2304 + i), y0, y1);
        g_idx[i]        = (int)(y0 & 255u);
        g_idx[2304 + i] = (int)(y1 & 255u);
    } else {
        int j2 = (b - 10) * 256 + tid;
        int jj = j2 & 3, u4 = j2 >> 2;
        int lane = u4 & 31, g = (u4 >> 5) & 15, nb = u4 >> 9;
        int n = nb * 8 + (lane >> 2);
        int kp = g * 16 + (lane & 3) + jj * 4;
        g_w2f[j2] = packbf(w2[n * 512 + 2 * kp], w2[n * 512 + 2 * kp + 1]);
    }
}

// ---- setup2: W1' = V@w1^T (+b1 folded), stored as B-frags ------------------
__global__ void setup2_kernel(const float *__restrict__ w1, const float *__restrict__ b1) {
    int gid = blockIdx.x * 256 + threadIdx.x;
    int lane = gid & 31, ntile = gid >> 5;
    int n = ntile * 8 + (lane >> 2), q = lane & 3;
    const float *w1n = w1 + n * 128;
    float d[4] = {0.f, 0.f, 0.f, 0.f};
    int ks[4] = {2 * q, 2 * q + 1, 2 * q + 8, 2 * q + 9};
#pragma unroll
    for (int m = 0; m < 4; ++m) {
        int k = ks[m];
        if (k < 12) {
            float s = 0.f;
            for (int c = 0; c < 128; ++c) s = fmaf(g_V[k * 128 + c], w1n[c], s);
            if (k == 11) s += b1[n];
            d[m] = s;
        }
    }
    g_w1f2[ntile * 32 + lane] = make_uint2(packbf(d[0], d[1]), packbf(d[2], d[3]));
}

// ------ attention (monotone M, reg top-18, softmax) + closed-form LN1 -------
__global__ void __launch_bounds__(256)
attn_kernel(const float *__restrict__ x) {
    __shared__ float xs[256];
    __shared__ float al[256 * 8];
    __shared__ int   midx[8][UK];
    __shared__ float zm[10], Gs[100];
    __shared__ float pmx[256], pmn[256], psm[256];
    int tid = threadIdx.x, lane = tid & 31, h = tid >> 5;
    int seq = blockIdx.x;
    xs[tid] = x[seq * 256 + tid];
    if (tid < 100) Gs[tid] = g_G[tid];
    if (tid >= 100 && tid < 110) zm[tid - 100] = g_zm[tid - 100];
    __syncthreads();

    // per-token sampled stats (head-independent): pmax, pmin, psum over 18 samples
    {
        float pm = -3.4e38f, pn = 3.4e38f, ps = 0.f;
        const int *ip = g_idx + tid * UK;
#pragma unroll
        for (int j = 0; j < UK; ++j) {
            float v = xs[ip[j]];
            pm = fmaxf(pm, v); pn = fminf(pn, v); ps += v;
        }
        pmx[tid] = pm; pmn[tid] = pn; psm[tid] = ps;
    }

    // block-wide sum/max/min of xs (every warp computes identical full result)
    float s = 0.f, xmax = -3.4e38f, xmin = 3.4e38f;
#pragma unroll
    for (int k = 0; k < 8; ++k) {
        float v = xs[lane + 32 * k];
        s += v; xmax = fmaxf(xmax, v); xmin = fminf(xmin, v);
    }
#pragma unroll
    for (int o = 16; o > 0; o >>= 1) {
        s += __shfl_xor_sync(0xffffffffu, s, o);
        xmax = fmaxf(xmax, __shfl_xor_sync(0xffffffffu, xmax, o));
        xmin = fminf(xmin, __shfl_xor_sync(0xffffffffu, xmin, o));
    }
    float xbar = s * (1.0f / 256.0f);
    __syncthreads();

    // M per (token, head) from closed form; warp h covers its head
    float c1 = g_c1[h], c2 = g_c2[h], c3 = g_c3[h], c4 = g_c4[h];
    float Mreg[8];
#pragma unroll
    for (int k = 0; k < 8; ++k) {
        int t = lane + 32 * k;
        float xl = xs[t];
        float A = fmaf(c1, xl, c3), Bc = fmaf(c2, xl, c4);
        float mx = (A >= 0.f ? A * pmx[t] : A * pmn[t]) + Bc;
        float sm = fmaf(A, psm[t], (float)UK * Bc);
        Mreg[k] = mx - sm * (1.0f / 256.0f);
        al[t * 8 + h] = xbar;
    }

    // register-resident serial top-18 (ties -> lowest index)
    for (int it = 0; it < UK; ++it) {
        float bv = -3.4e38f; int bi = 256;
#pragma unroll
        for (int k = 0; k < 8; ++k) {
            int t = lane + 32 * k;
            if (Mreg[k] > bv) { bv = Mreg[k]; bi = t; }
        }
#pragma unroll
        for (int o = 16; o > 0; o >>= 1) {
            float ov = __shfl_xor_sync(0xffffffffu, bv, o);
            int   oi = __shfl_xor_sync(0xffffffffu, bi, o);
            if (ov > bv || (ov == bv && oi < bi)) { bv = ov; bi = oi; }
        }
#pragma unroll
        for (int k = 0; k < 8; ++k)
            if ((bi >> 5) == k && (bi & 31) == lane) Mreg[k] = -3.4e38f;
        if (lane == 0) midx[h][it] = bi;
    }
    __syncthreads();

    // 144 softmax rows; softmax(A*xs) (affine shift cancels), 2-row ILP
#pragma unroll
    for (int i = 0; i < 9; ++i) {
        int pa = h + 16 * i, pb = pa + 8;
        int ha = pa / UK, ita = pa % UK;
        int hb = pb / UK, itb = pb % UK;
        int ma = midx[ha][ita], mb = midx[hb][itb];
        float Aa = 0.25f * fmaf(g_c1[ha], xs[ma], g_c3[ha]);
        float Ab = 0.25f * fmaf(g_c1[hb], xs[mb], g_c3[hb]);
        float rma = (Aa >= 0.f) ? Aa * xmax : Aa * xmin;
        float rmb = (Ab >= 0.f) ? Ab * xmax : Ab * xmin;
        float Za = 0.f, Sa = 0.f, Zb = 0.f, Sb = 0.f;
#pragma unroll
        for (int k = 0; k < 8; ++k) {
            float xv = xs[lane + 32 * k];
            float ea = __expf(fmaf(Aa, xv, -rma));
            float eb = __expf(fmaf(Ab, xv, -rmb));
            Za += ea; Sa += ea * xv;
            Zb += eb; Sb += eb * xv;
        }
#pragma unroll
        for (int o = 16; o > 0; o >>= 1) {
            Za += __shfl_xor_sync(0xffffffffu, Za, o);
            Sa += __shfl_xor_sync(0xffffffffu, Sa, o);
            Zb += __shfl_xor_sync(0xffffffffu, Zb, o);
            Sb += __shfl_xor_sync(0xffffffffu, Sb, o);
        }
        if (lane == 0) {
            al[ma * 8 + ha] = Sa / Za;
            al[mb * 8 + hb] = Sb / Zb;
        }
    }
    __syncthreads();

    // closed-form LN1 stats for token tid: y = [x, a1..8, 1]
    float y[10];
    y[0] = xs[tid];
#pragma unroll
    for (int hh = 0; hh < 8; ++hh) y[1 + hh] = al[tid * 8 + hh];
    y[9] = 1.f;
    float mu = 0.f;
#pragma unroll
    for (int i = 0; i < 10; ++i) mu = fmaf(y[i], zm[i], mu);
    float q2 = 0.f;
#pragma unroll
    for (int i = 0; i < 10; ++i) {
        float acc = 0.f;
#pragma unroll
        for (int j = 0; j < 10; ++j) acc = fmaf(Gs[i * 10 + j], y[j], acc);
        q2 = fmaf(y[i], acc, q2);
    }
    float var = q2 - mu * mu;
    float r = rsqrtf(var + 1e-5f);
    float u[12];
#pragma unroll
    for (int i = 0; i < 9; ++i) u[i] = y[i] * r;
    u[9] = r; u[10] = -mu * r; u[11] = 1.f;

    size_t row = (size_t)seq * 256 + tid;
    float4 *up = (float4 *)(g_u + row * 12);
    up[0] = make_float4(u[0], u[1], u[2], u[3]);
    up[1] = make_float4(u[4], u[5], u[6], u[7]);
    up[2] = make_float4(u[8], u[9], u[10], u[11]);
    uint4 *ub = (uint4 *)(g_ubf + row * 8);
    ub[0] = make_uint4(packbf(u[0], u[1]), packbf(u[2], u[3]),
                       packbf(u[4], u[5]), packbf(u[6], u[7]));
    ub[1] = make_uint4(packbf(u[8], u[9]), packbf(u[10], u[11]), 0u, 0u);
}

// ---------- FFN + residual + LN2; GEMM1 K=16 (rank-12), GEMM2 K=512 --------
#define TS_U32 (64 * 260)
#define YS_STRIDE 132
#define OFF_US (TS_U32)
#define OFF_VS (OFF_US + 64 * 12)
#define OFF_B2 (OFF_VS + 12 * 128)
#define OFF_LG (OFF_B2 + 128)
#define OFF_LB (OFF_LG + 128)
#define FFN_SMEM ((OFF_LB + 128) * 4)

__global__ void __launch_bounds__(256)
ffn_kernel(const float *__restrict__ b2,
           const float *__restrict__ ln2g, const float *__restrict__ ln2b) {
    extern __shared__ unsigned ts[];   // [64][260] bf16x2; later ys fp32 [64][132]
    float *us  = (float *)(ts + OFF_US);
    float *Vs  = (float *)(ts + OFF_VS);
    float *b2s = (float *)(ts + OFF_B2);
    float *lgs = (float *)(ts + OFF_LG);
    float *lbs = (float *)(ts + OFF_LB);
    int tid = threadIdx.x;
    int wid = tid >> 5, lane = tid & 31;
    int row0 = blockIdx.x * 64;
    int r = lane >> 2, q = lane & 3;
    int ms = wid & 3, nh = wid >> 2;

    for (int i = tid; i < 64 * 12; i += 256) us[i] = g_u[(size_t)row0 * 12 + i];
    for (int i = tid; i < 12 * 128; i += 256) Vs[i] = g_V[i];
    if (tid < 128) { b2s[tid] = b2[tid]; lgs[tid] = ln2g[tid]; lbs[tid] = ln2b[tid]; }

    // GEMM1: U[64,16] @ W1'^T -> relu -> ts bf16 [64][512]
    {
        unsigned a0, a1, a2, a3;
        const unsigned *U = g_ubf + (size_t)(row0 + ms * 16) * 8;
        a0 = U[r * 8 + q];
        a1 = U[(r + 8) * 8 + q];
        a2 = U[r * 8 + q + 4];
        a3 = U[(r + 8) * 8 + q + 4];
#pragma unroll 8
        for (int t = 0; t < 32; ++t) {
            int nb = nh * 32 + t;
            uint2 B = g_w1f2[nb * 32 + lane];
            float d0 = 0.f, d1 = 0.f, d2 = 0.f, d3 = 0.f;
            mma16816(d0, d1, d2, d3, a0, a1, a2, a3, B.x, B.y);
            d0 = fmaxf(d0, 0.f); d1 = fmaxf(d1, 0.f);
            d2 = fmaxf(d2, 0.f); d3 = fmaxf(d3, 0.f);
            ts[(ms * 16 + r) * 260 + nb * 4 + q]     = packbf(d0, d1);
            ts[(ms * 16 + r + 8) * 260 + nb * 4 + q] = packbf(d2, d3);
        }
    }
    __syncthreads();

    // GEMM2: T[64,512] @ w2^T via ldmatrix A-frags
    float d[8][4];
#pragma unroll
    for (int t = 0; t < 8; ++t) { d[t][0]=0.f; d[t][1]=0.f; d[t][2]=0.f; d[t][3]=0.f; }
    {
        uint32_t lmbase = smem_u32(ts)
            + (uint32_t)((ms * 16 + ((lane >> 3) & 1) * 8 + (lane & 7)) * 1040)
            + (uint32_t)(((lane >> 4) & 1) * 16);
        const uint4 *W2 = (const uint4 *)g_w2f;
#pragma unroll 2
        for (int g = 0; g < 16; ++g) {
            unsigned a0[4], a1[4];
            LDMX4(a0, lmbase + (2 * g) * 32);
            LDMX4(a1, lmbase + (2 * g) * 32 + 32);
#pragma unroll
            for (int t = 0; t < 8; ++t) {
                uint4 B = W2[(((nh * 8 + t) * 16) + g) * 32 + lane];
                mma16816(d[t][0], d[t][1], d[t][2], d[t][3],
                         a0[0], a0[1], a0[2], a0[3], B.x, B.y);
                mma16816(d[t][0], d[t][1], d[t][2], d[t][3],
                         a1[0], a1[1], a1[2], a1[3], B.z, B.w);
            }
        }
    }
    __syncthreads();

    // ys = y + b2 + residual (x1 = u@V fp32); reuse ts as fp32 [64][132]
    float *ys = (float *)ts;
    {
        int rr = ms * 16 + r;
        float u0[12], u1[12];
#pragma unroll
        for (int k = 0; k < 12; ++k) { u0[k] = us[rr * 12 + k]; u1[k] = us[(rr + 8) * 12 + k]; }
#pragma unroll
        for (int t = 0; t < 8; ++t) {
            int c0 = (nh * 8 + t) * 8 + q * 2;
            float x00 = 0.f, x01 = 0.f, x10 = 0.f, x11 = 0.f;
#pragma unroll
            for (int k = 0; k < 12; ++k) {
                float v0 = Vs[k * 128 + c0], v1 = Vs[k * 128 + c0 + 1];
                x00 = fmaf(u0[k], v0, x00); x01 = fmaf(u0[k], v1, x01);
                x10 = fmaf(u1[k], v0, x10); x11 = fmaf(u1[k], v1, x11);
            }
            float bbx = b2s[c0], bby = b2s[c0 + 1];
            ys[rr * YS_STRIDE + c0]           = d[t][0] + bbx + x00;
            ys[rr * YS_STRIDE + c0 + 1]       = d[t][1] + bby + x01;
            ys[(rr + 8) * YS_STRIDE + c0]     = d[t][2] + bbx + x10;
            ys[(rr + 8) * YS_STRIDE + c0 + 1] = d[t][3] + bby + x11;
        }
    }
    __syncthreads();

    // LN2: 8 warps x 8 rows
#pragma unroll
    for (int jj = 0; jj < 8; ++jj) {
        int rr = wid * 8 + jj;
        float z[4];
#pragma unroll
        for (int j = 0; j < 4; ++j) z[j] = ys[rr * YS_STRIDE + lane + 32 * j];
        float s2 = z[0] + z[1] + z[2] + z[3];
#pragma unroll
        for (int o = 16; o > 0; o >>= 1) s2 += __shfl_xor_sync(0xffffffffu, s2, o);
        float mu = s2 * (1.0f / 128.0f);
        float v = 0.f;
#pragma unroll
        for (int j = 0; j < 4; ++j) { float dd = z[j] - mu; v += dd * dd; }
#pragma unroll
        for (int o = 16; o > 0; o >>= 1) v += __shfl_xor_sync(0xffffffffu, v, o);
        float rstd = rsqrtf(v * (1.0f / 128.0f) + 1e-5f);
#pragma unroll
        for (int j = 0; j < 4; ++j) {
            int c = lane + 32 * j;
            g_out2[(size_t)(row0 + rr) * 128 + c] = (z[j] - mu) * rstd * lgs[c] + lbs[c];
        }
    }
}

// ----- out[b,c,t] = sum_n out2[((b*32+n)*256+t)*128 + c]; float4 tree ------
__global__ void reduce_kernel(float *__restrict__ out) {
    __shared__ float4 sh[4 * 32];
    int t = blockIdx.x & 255, b = blockIdx.x >> 8;
    int c4 = threadIdx.x & 31, grp = threadIdx.x >> 5;
    const float *base = g_out2 + ((size_t)(b * 32 + grp * 4) * 256 + t) * 128 + c4 * 4;
    float4 acc = make_float4(0.f, 0.f, 0.f, 0.f);
#pragma unroll
    for (int n = 0; n < 4; ++n) {
        float4 v = *(const float4 *)(base + (size_t)n * 256 * 128);
        acc.x += v.x; acc.y += v.y; acc.z += v.z; acc.w += v.w;
    }
    if (grp >= 4) sh[(grp - 4) * 32 + c4] = acc;
    __syncthreads();
    if (grp < 4) {
        float4 v = sh[grp * 32 + c4];
        acc.x += v.x; acc.y += v.y; acc.z += v.z; acc.w += v.w;
    }
    __syncthreads();
    if (grp >= 2 && grp < 4) sh[(grp - 2) * 32 + c4] = acc;
    __syncthreads();
    if (grp < 2) {
        float4 v = sh[grp * 32 + c4];
        acc.x += v.x; acc.y += v.y; acc.z += v.z; acc.w += v.w;
    }
    __syncthreads();
    if (grp == 1) sh[c4] = acc;
    __syncthreads();
    if (grp == 0) {
        float4 v = sh[c4];
        acc.x += v.x; acc.y += v.y; acc.z += v.z; acc.w += v.w;
        int cb = c4 * 4;
        out[((b * 128 + cb + 0) << 8) + t] = acc.x;
        out[((b * 128 + cb + 1) << 8) + t] = acc.y;
        out[((b * 128 + cb + 2) << 8) + t] = acc.z;
        out[((b * 128 + cb + 3) << 8) + t] = acc.w;
    }
}

extern "C" void kernel_launch(void* const* d_in, const int* in_sizes, int n_in,
                              void* d_out, int out_size) {
    const float *x     = (const float *)d_in[0];
    const float *mlp_w = (const float *)d_in[1];
    const float *mlp_b = (const float *)d_in[2];
    const float *wq = (const float *)d_in[3],  *bq = (const float *)d_in[4];
    const float *wk = (const float *)d_in[5],  *bk = (const float *)d_in[6];
    const float *wv = (const float *)d_in[7],  *bv = (const float *)d_in[8];
    const float *wo = (const float *)d_in[9],  *bo = (const float *)d_in[10];
    const float *w1 = (const float *)d_in[11], *b1 = (const float *)d_in[12];
    const float *w2 = (const float *)d_in[13], *b2 = (const float *)d_in[14];
    const float *ln1g = (const float *)d_in[15], *ln1b = (const float *)d_in[16];
    const float *ln2g = (const float *)d_in[17], *ln2b = (const float *)d_in[18];
    float *out = (float *)d_out;

    cudaFuncSetAttribute(ffn_kernel, cudaFuncAttributeMaxDynamicSharedMemorySize, FFN_SMEM);

    setup1_kernel<<<138, 256>>>(mlp_w, mlp_b, wq, bq, wk, bk, wv, bv, wo, bo,
                                ln1g, ln1b, w2);
    setup2_kernel<<<8, 256>>>(w1, b1);
    attn_kernel<<<128, 256>>>(x);
    ffn_kernel<<<TOK / 64, 256, FFN_SMEM>>>(b2, ln2g, ln2b);
    reduce_kernel<<<4 * 256, 256>>>(out);
}

// round 8
// speedup vs baseline: 8.2095x; 2.3237x over previous
#include <cuda_runtime.h>
#include <cuda_bf16.h>
#include <math.h>
#include <cstdint>

// InformerLayer: b=4,N=32,T=256 -> B=128 seqs, L=256, C=128, H=8, E=16, DFF=512, u=k=18
#define TOK 32768
#define UK  18

__device__ float g_Aq[128], g_Bq[128], g_Ak[128], g_Bk[128], g_Av[128], g_Bv[128];
__device__ float g_c1[8], g_c2[8], g_c3[8], g_c4[8];
__device__ float g_Po[8 * 128], g_Co[128];
__device__ int   g_idx[256 * UK];
__device__ float g_zm[10];           // mean of z-basis rows
__device__ float g_G[100];           // Gram matrix of z-basis rows (/128)
__device__ float g_V[12 * 128];      // x1 = u @ V
__device__ float g_u[TOK * 12];      // per-row coefficients (fp32)
__device__ unsigned g_ubf[TOK * 8];  // u padded to 16, bf16x2
__device__ float g_out2[TOK * 128];
__device__ uint2 g_w1f2[64 * 32];            // W1' B-frags: [ntile][lane]
__device__ unsigned g_w2f[16 * 16 * 32 * 4]; // w2 B-frags: [nb][g][lane][4]

static __device__ __forceinline__ unsigned packbf(float a, float b) {
    __nv_bfloat162 t = __floats2bfloat162_rn(a, b);
    return *reinterpret_cast<unsigned *>(&t);
}

__device__ __forceinline__ void mma16816(float &d0, float &d1, float &d2, float &d3,
                                         unsigned a0, unsigned a1, unsigned a2, unsigned a3,
                                         unsigned b0, unsigned b1) {
    asm volatile("mma.sync.aligned.m16n8k16.row.col.f32.bf16.bf16.f32 "
                 "{%0,%1,%2,%3},{%4,%5,%6,%7},{%8,%9},{%0,%1,%2,%3};"
                 : "+f"(d0), "+f"(d1), "+f"(d2), "+f"(d3)
                 : "r"(a0), "r"(a1), "r"(a2), "r"(a3), "r"(b0), "r"(b1));
}

#define LDMX4(r, addr) \
    asm volatile("ldmatrix.sync.aligned.m8n8.x4.shared.b16 {%0,%1,%2,%3}, [%4];" \
                 : "=r"((r)[0]), "=r"((r)[1]), "=r"((r)[2]), "=r"((r)[3]) : "r"(addr))

static __device__ __forceinline__ uint32_t smem_u32(const void *p) {
    uint32_t a;
    asm("{ .reg .u64 t; cvta.to.shared.u64 t, %1; cvt.u32.u64 %0, t; }" : "=r"(a) : "l"(p));
    return a;
}

// ------------------------------- Threefry ---------------------------------
__device__ __forceinline__ void tf_r(unsigned &x0, unsigned &x1, int r) {
    x0 += x1; x1 = (x1 << r) | (x1 >> (32 - r)); x1 ^= x0;
}
__device__ void threefry2x32(unsigned k0, unsigned k1, unsigned c0, unsigned c1,
                             unsigned &o0, unsigned &o1) {
    unsigned ks2 = k0 ^ k1 ^ 0x1BD11BDAu;
    unsigned x0 = c0 + k0, x1 = c1 + k1;
    tf_r(x0,x1,13); tf_r(x0,x1,15); tf_r(x0,x1,26); tf_r(x0,x1,6);
    x0 += k1;  x1 += ks2 + 1u;
    tf_r(x0,x1,17); tf_r(x0,x1,29); tf_r(x0,x1,16); tf_r(x0,x1,24);
    x0 += ks2; x1 += k0 + 2u;
    tf_r(x0,x1,13); tf_r(x0,x1,15); tf_r(x0,x1,26); tf_r(x0,x1,6);
    x0 += k0;  x1 += k1 + 3u;
    tf_r(x0,x1,17); tf_r(x0,x1,29); tf_r(x0,x1,16); tf_r(x0,x1,24);
    x0 += k1;  x1 += ks2 + 4u;
    tf_r(x0,x1,13); tf_r(x0,x1,15); tf_r(x0,x1,26); tf_r(x0,x1,6);
    x0 += ks2; x1 += k0 + 5u;
    o0 = x0; o1 = x1;
}

// ---- setup_a: Aq..Bv (warp/c, coalesced) + threefry idx + w2 frags ---------
__global__ void __launch_bounds__(256)
setup_a(const float *__restrict__ mlp_w, const float *__restrict__ mlp_b,
        const float *__restrict__ wq, const float *__restrict__ bq,
        const float *__restrict__ wk, const float *__restrict__ bk,
        const float *__restrict__ wv, const float *__restrict__ bv,
        const float *__restrict__ w2) {
    int b = blockIdx.x, tid = threadIdx.x, lane = tid & 31, wid = tid >> 5;
    if (b < 16) {
        int c = b * 8 + wid;
        float aq = 0.f, bq2 = 0.f, ak = 0.f, bk2 = 0.f, av = 0.f, bv2 = 0.f;
#pragma unroll
        for (int m = 0; m < 4; ++m) {
            int j = lane + 32 * m;
            float mw = mlp_w[j], mb = mlp_b[j];
            float q = wq[c * 128 + j], k = wk[c * 128 + j], v = wv[c * 128 + j];
            aq = fmaf(mw, q, aq); bq2 = fmaf(mb, q, bq2);
            ak = fmaf(mw, k, ak); bk2 = fmaf(mb, k, bk2);
            av = fmaf(mw, v, av); bv2 = fmaf(mb, v, bv2);
        }
#pragma unroll
        for (int o = 16; o > 0; o >>= 1) {
            aq  += __shfl_xor_sync(0xffffffffu, aq, o);
            bq2 += __shfl_xor_sync(0xffffffffu, bq2, o);
            ak  += __shfl_xor_sync(0xffffffffu, ak, o);
            bk2 += __shfl_xor_sync(0xffffffffu, bk2, o);
            av  += __shfl_xor_sync(0xffffffffu, av, o);
            bv2 += __shfl_xor_sync(0xffffffffu, bv2, o);
        }
        if (lane == 0) {
            g_Aq[c] = aq; g_Bq[c] = bq2 + bq[c];
            g_Ak[c] = ak; g_Bk[c] = bk2 + bk[c];
            g_Av[c] = av; g_Bv[c] = bv2 + bv[c];
        }
    } else if (b < 25) {
        int i = (b - 16) * 256 + tid;
        unsigned a0, a1, b0, b1;
        threefry2x32(0u, 42u, 0u, 2u, a0, a1);
        threefry2x32(0u, 42u, 1u, 3u, b0, b1);
        unsigned y0, y1;
        threefry2x32(a1, b1, (unsigned)i, (unsigned)(2304 + i), y0, y1);
        g_idx[i]        = (int)(y0 & 255u);
        g_idx[2304 + i] = (int)(y1 & 255u);
    } else {
        int j2 = (b - 25) * 256 + tid;
        int jj = j2 & 3, u4 = j2 >> 2;
        int ln = u4 & 31, g = (u4 >> 5) & 15, nb = u4 >> 9;
        int n = nb * 8 + (ln >> 2);
        int kp = g * 16 + (ln & 3) + jj * 4;
        g_w2f[j2] = packbf(w2[n * 512 + 2 * kp], w2[n * 512 + 2 * kp + 1]);
    }
}

// ---- setup_b: Co + Po (warp/c, wo row read once) + c1..c4 ------------------
__global__ void __launch_bounds__(256)
setup_b(const float *__restrict__ wo, const float *__restrict__ bo) {
    int b = blockIdx.x, tid = threadIdx.x, lane = tid & 31, wid = tid >> 5;
    if (b < 16) {
        int c = b * 8 + wid;
        float co = 0.f, pv[4];
#pragma unroll
        for (int m = 0; m < 4; ++m) {
            int j = lane + 32 * m;
            float w = wo[c * 128 + j];
            co = fmaf(g_Bv[j], w, co);
            pv[m] = g_Av[j] * w;     // contributes to head (lane+32m)>>4
        }
#pragma unroll
        for (int o = 16; o > 0; o >>= 1) co += __shfl_xor_sync(0xffffffffu, co, o);
#pragma unroll
        for (int o = 8; o > 0; o >>= 1)
#pragma unroll
            for (int m = 0; m < 4; ++m) pv[m] += __shfl_xor_sync(0xffffffffu, pv[m], o);
        if ((lane & 15) == 0) {
            int hb = lane >> 4;      // 0 or 1
#pragma unroll
            for (int m = 0; m < 4; ++m) g_Po[(hb + 2 * m) * 128 + c] = pv[m];
        }
        if (lane == 0) g_Co[c] = co + bo[c];
    } else {
        if (tid < 8) {
            int h = tid;
            float c1 = 0.f, c2 = 0.f, c3 = 0.f, c4 = 0.f;
            for (int e = 0; e < 16; ++e) {
                int i = h * 16 + e;
                c1 += g_Aq[i] * g_Ak[i];
                c2 += g_Aq[i] * g_Bk[i];
                c3 += g_Bq[i] * g_Ak[i];
                c4 += g_Bq[i] * g_Bk[i];
            }
            g_c1[h] = c1; g_c2[h] = c2; g_c3[h] = c3; g_c4[h] = c4;
        }
    }
}

// z-basis element
static __device__ __forceinline__ float zb(int i, int c,
                                           const float *mlp_w, const float *mlp_b) {
    if (i == 0) return mlp_w[c];
    if (i <= 8) return g_Po[(i - 1) * 128 + c];
    return mlp_b[c] + g_Co[c];
}

// ---- setup_c: V rows + Gram matrix / means (warp per entry) ----------------
__global__ void __launch_bounds__(256)
setup_c(const float *__restrict__ mlp_w, const float *__restrict__ mlp_b,
        const float *__restrict__ ln1g, const float *__restrict__ ln1b) {
    int b = blockIdx.x, tid = threadIdx.x, lane = tid & 31, wid = tid >> 5;
    if (b == 0) {
        if (tid < 128) {
            int c = tid;
            float K = mlp_b[c] + g_Co[c];
            float g = ln1g[c];
            g_V[0 * 128 + c] = mlp_w[c] * g;
#pragma unroll
            for (int h = 0; h < 8; ++h) g_V[(1 + h) * 128 + c] = g_Po[h * 128 + c] * g;
            g_V[9 * 128 + c]  = K * g;
            g_V[10 * 128 + c] = g;
            g_V[11 * 128 + c] = ln1b[c];
        }
    } else {
        int task = (b - 1) * 8 + wid;   // 112 warps for 110 tasks
        if (task < 100) {
            int i = task / 10, j = task % 10;
            float s = 0.f;
#pragma unroll
            for (int m = 0; m < 4; ++m) {
                int c = lane + 32 * m;
                s = fmaf(zb(i, c, mlp_w, mlp_b), zb(j, c, mlp_w, mlp_b), s);
            }
#pragma unroll
            for (int o = 16; o > 0; o >>= 1) s += __shfl_xor_sync(0xffffffffu, s, o);
            if (lane == 0) g_G[task] = s * (1.0f / 128.0f);
        } else if (task < 110) {
            int i = task - 100;
            float s = 0.f;
#pragma unroll
            for (int m = 0; m < 4; ++m) s += zb(i, lane + 32 * m, mlp_w, mlp_b);
#pragma unroll
            for (int o = 16; o > 0; o >>= 1) s += __shfl_xor_sync(0xffffffffu, s, o);
            if (lane == 0) g_zm[i] = s * (1.0f / 128.0f);
        }
    }
}

// ---- setup_d: W1' = V@w1^T (+b1), warp per n-row, frag packing -------------
__global__ void __launch_bounds__(256)
setup_d(const float *__restrict__ w1, const float *__restrict__ b1) {
    __shared__ float s[8][12];
    int tid = threadIdx.x, lane = tid & 31, wid = tid >> 5;
    int n = blockIdx.x * 8 + wid;
    float4 wv = *(const float4 *)(w1 + n * 128 + lane * 4);
    float p[12];
#pragma unroll
    for (int k = 0; k < 12; ++k) {
        float4 v = *(const float4 *)(g_V + k * 128 + lane * 4);
        p[k] = wv.x * v.x + wv.y * v.y + wv.z * v.z + wv.w * v.w;
    }
#pragma unroll
    for (int o = 16; o > 0; o >>= 1)
#pragma unroll
        for (int k = 0; k < 12; ++k) p[k] += __shfl_xor_sync(0xffffffffu, p[k], o);
    if (lane == 0) {
#pragma unroll
        for (int k = 0; k < 11; ++k) s[wid][k] = p[k];
        s[wid][11] = p[11] + b1[n];
    }
    __syncthreads();
    if (wid == 0) {
        int nr = lane >> 2, q = lane & 3;
        float d0 = s[nr][2 * q], d1 = s[nr][2 * q + 1];
        float d2 = (2 * q + 8 < 12) ? s[nr][2 * q + 8] : 0.f;
        float d3 = (2 * q + 9 < 12) ? s[nr][2 * q + 9] : 0.f;
        g_w1f2[blockIdx.x * 32 + lane] = make_uint2(packbf(d0, d1), packbf(d2, d3));
    }
}

// ------ attention (monotone M, reg top-18, softmax) + closed-form LN1 -------
__global__ void __launch_bounds__(256)
attn_kernel(const float *__restrict__ x) {
    __shared__ float xs[256];
    __shared__ float al[256 * 8];
    __shared__ int   midx[8][UK];
    __shared__ float zm[10], Gs[100];
    __shared__ float pmx[256], pmn[256], psm[256];
    int tid = threadIdx.x, lane = tid & 31, h = tid >> 5;
    int seq = blockIdx.x;
    xs[tid] = x[seq * 256 + tid];
    if (tid < 100) Gs[tid] = g_G[tid];
    if (tid >= 100 && tid < 110) zm[tid - 100] = g_zm[tid - 100];
    __syncthreads();

    {
        float pm = -3.4e38f, pn = 3.4e38f, ps = 0.f;
        const int *ip = g_idx + tid * UK;
#pragma unroll
        for (int j = 0; j < UK; ++j) {
            float v = xs[ip[j]];
            pm = fmaxf(pm, v); pn = fminf(pn, v); ps += v;
        }
        pmx[tid] = pm; pmn[tid] = pn; psm[tid] = ps;
    }

    float s = 0.f, xmax = -3.4e38f, xmin = 3.4e38f;
#pragma unroll
    for (int k = 0; k < 8; ++k) {
        float v = xs[lane + 32 * k];
        s += v; xmax = fmaxf(xmax, v); xmin = fminf(xmin, v);
    }
#pragma unroll
    for (int o = 16; o > 0; o >>= 1) {
        s += __shfl_xor_sync(0xffffffffu, s, o);
        xmax = fmaxf(xmax, __shfl_xor_sync(0xffffffffu, xmax, o));
        xmin = fminf(xmin, __shfl_xor_sync(0xffffffffu, xmin, o));
    }
    float xbar = s * (1.0f / 256.0f);
    __syncthreads();

    float c1 = g_c1[h], c2 = g_c2[h], c3 = g_c3[h], c4 = g_c4[h];
    float Mreg[8];
#pragma unroll
    for (int k = 0; k < 8; ++k) {
        int t = lane + 32 * k;
        float xl = xs[t];
        float A = fmaf(c1, xl, c3), Bc = fmaf(c2, xl, c4);
        float mx = (A >= 0.f ? A * pmx[t] : A * pmn[t]) + Bc;
        float sm = fmaf(A, psm[t], (float)UK * Bc);
        Mreg[k] = mx - sm * (1.0f / 256.0f);
        al[t * 8 + h] = xbar;
    }

    for (int it = 0; it < UK; ++it) {
        float bv = -3.4e38f; int bi = 256;
#pragma unroll
        for (int k = 0; k < 8; ++k) {
            int t = lane + 32 * k;
            if (Mreg[k] > bv) { bv = Mreg[k]; bi = t; }
        }
#pragma unroll
        for (int o = 16; o > 0; o >>= 1) {
            float ov = __shfl_xor_sync(0xffffffffu, bv, o);
            int   oi = __shfl_xor_sync(0xffffffffu, bi, o);
            if (ov > bv || (ov == bv && oi < bi)) { bv = ov; bi = oi; }
        }
#pragma unroll
        for (int k = 0; k < 8; ++k)
            if ((bi >> 5) == k && (bi & 31) == lane) Mreg[k] = -3.4e38f;
        if (lane == 0) midx[h][it] = bi;
    }
    __syncthreads();

#pragma unroll
    for (int i = 0; i < 9; ++i) {
        int pa = h + 16 * i, pb = pa + 8;
        int ha = pa / UK, ita = pa % UK;
        int hb = pb / UK, itb = pb % UK;
        int ma = midx[ha][ita], mb = midx[hb][itb];
        float Aa = 0.25f * fmaf(g_c1[ha], xs[ma], g_c3[ha]);
        float Ab = 0.25f * fmaf(g_c1[hb], xs[mb], g_c3[hb]);
        float rma = (Aa >= 0.f) ? Aa * xmax : Aa * xmin;
        float rmb = (Ab >= 0.f) ? Ab * xmax : Ab * xmin;
        float Za = 0.f, Sa = 0.f, Zb = 0.f, Sb = 0.f;
#pragma unroll
        for (int k = 0; k < 8; ++k) {
            float xv = xs[lane + 32 * k];
            float ea = __expf(fmaf(Aa, xv, -rma));
            float eb = __expf(fmaf(Ab, xv, -rmb));
            Za += ea; Sa += ea * xv;
            Zb += eb; Sb += eb * xv;
        }
#pragma unroll
        for (int o = 16; o > 0; o >>= 1) {
            Za += __shfl_xor_sync(0xffffffffu, Za, o);
            Sa += __shfl_xor_sync(0xffffffffu, Sa, o);
            Zb += __shfl_xor_sync(0xffffffffu, Zb, o);
            Sb += __shfl_xor_sync(0xffffffffu, Sb, o);
        }
        if (lane == 0) {
            al[ma * 8 + ha] = Sa / Za;
            al[mb * 8 + hb] = Sb / Zb;
        }
    }
    __syncthreads();

    float y[10];
    y[0] = xs[tid];
#pragma unroll
    for (int hh = 0; hh < 8; ++hh) y[1 + hh] = al[tid * 8 + hh];
    y[9] = 1.f;
    float mu = 0.f;
#pragma unroll
    for (int i = 0; i < 10; ++i) mu = fmaf(y[i], zm[i], mu);
    float q2 = 0.f;
#pragma unroll
    for (int i = 0; i < 10; ++i) {
        float acc = 0.f;
#pragma unroll
        for (int j = 0; j < 10; ++j) acc = fmaf(Gs[i * 10 + j], y[j], acc);
        q2 = fmaf(y[i], acc, q2);
    }
    float var = q2 - mu * mu;
    float r = rsqrtf(var + 1e-5f);
    float u[12];
#pragma unroll
    for (int i = 0; i < 9; ++i) u[i] = y[i] * r;
    u[9] = r; u[10] = -mu * r; u[11] = 1.f;

    size_t row = (size_t)seq * 256 + tid;
    float4 *up = (float4 *)(g_u + row * 12);
    up[0] = make_float4(u[0], u[1], u[2], u[3]);
    up[1] = make_float4(u[4], u[5], u[6], u[7]);
    up[2] = make_float4(u[8], u[9], u[10], u[11]);
    uint4 *ub = (uint4 *)(g_ubf + row * 8);
    ub[0] = make_uint4(packbf(u[0], u[1]), packbf(u[2], u[3]),
                       packbf(u[4], u[5]), packbf(u[6], u[7]));
    ub[1] = make_uint4(packbf(u[8], u[9]), packbf(u[10], u[11]), 0u, 0u);
}

// ---------- FFN + residual + LN2; 32 rows/block for 50% occupancy ----------
#define OFF_US (32 * 260)
#define OFF_VS (OFF_US + 32 * 12)
#define OFF_B2 (OFF_VS + 12 * 128)
#define OFF_LG (OFF_B2 + 128)
#define OFF_LB (OFF_LG + 128)
#define FFN_U32 (OFF_LB + 128)

__global__ void __launch_bounds__(256)
ffn_kernel(const float *__restrict__ b2,
           const float *__restrict__ ln2g, const float *__restrict__ ln2b) {
    __shared__ unsigned ts[FFN_U32];   // [32][260] bf16x2; later ys fp32 [32][132]
    float *us  = (float *)(ts + OFF_US);
    float *Vs  = (float *)(ts + OFF_VS);
    float *b2s = (float *)(ts + OFF_B2);
    float *lgs = (float *)(ts + OFF_LG);
    float *lbs = (float *)(ts + OFF_LB);
    int tid = threadIdx.x;
    int wid = tid >> 5, lane = tid & 31;
    int row0 = blockIdx.x * 32;
    int r = lane >> 2, q = lane & 3;
    int ms = wid >> 2, nq = wid & 3;

    for (int i = tid; i < 32 * 12; i += 256) us[i] = g_u[(size_t)row0 * 12 + i];
    for (int i = tid; i < 12 * 128; i += 256) Vs[i] = g_V[i];
    if (tid < 128) { b2s[tid] = b2[tid]; lgs[tid] = ln2g[tid]; lbs[tid] = ln2b[tid]; }

    // GEMM1: U[32,16] @ W1'^T -> relu -> ts bf16 [32][512]
    {
        const unsigned *U = g_ubf + (size_t)(row0 + ms * 16) * 8;
        unsigned a0 = U[r * 8 + q];
        unsigned a1 = U[(r + 8) * 8 + q];
        unsigned a2 = U[r * 8 + q + 4];
        unsigned a3 = U[(r + 8) * 8 + q + 4];
#pragma unroll 4
        for (int t = 0; t < 16; ++t) {
            int nb = nq * 16 + t;
            uint2 B = g_w1f2[nb * 32 + lane];
            float d0 = 0.f, d1 = 0.f, d2 = 0.f, d3 = 0.f;
            mma16816(d0, d1, d2, d3, a0, a1, a2, a3, B.x, B.y);
            d0 = fmaxf(d0, 0.f); d1 = fmaxf(d1, 0.f);
            d2 = fmaxf(d2, 0.f); d3 = fmaxf(d3, 0.f);
            ts[(ms * 16 + r) * 260 + nb * 4 + q]     = packbf(d0, d1);
            ts[(ms * 16 + r + 8) * 260 + nb * 4 + q] = packbf(d2, d3);
        }
    }
    __syncthreads();

    // GEMM2: T[32,512] @ w2^T; warp covers rows [ms*16,+16), cols [nq*32,+32)
    float d[4][4];
#pragma unroll
    for (int t = 0; t < 4; ++t) { d[t][0]=0.f; d[t][1]=0.f; d[t][2]=0.f; d[t][3]=0.f; }
    {
        uint32_t lmbase = smem_u32(ts)
            + (uint32_t)((ms * 16 + ((lane >> 3) & 1) * 8 + (lane & 7)) * 1040)
            + (uint32_t)(((lane >> 4) & 1) * 16);
        const uint4 *W2 = (const uint4 *)g_w2f;
#pragma unroll 2
        for (int g = 0; g < 16; ++g) {
            unsigned a0v[4], a1v[4];
            LDMX4(a0v, lmbase + 64 * g);
            LDMX4(a1v, lmbase + 64 * g + 32);
#pragma unroll
            for (int t = 0; t < 4; ++t) {
                uint4 B = W2[(((nq * 4 + t) * 16) + g) * 32 + lane];
                mma16816(d[t][0], d[t][1], d[t][2], d[t][3],
                         a0v[0], a0v[1], a0v[2], a0v[3], B.x, B.y);
                mma16816(d[t][0], d[t][1], d[t][2], d[t][3],
                         a1v[0], a1v[1], a1v[2], a1v[3], B.z, B.w);
            }
        }
    }
    __syncthreads();

    // ys = y + b2 + residual (x1 = u@V fp32); reuse ts as fp32 [32][132]
    float *ys = (float *)ts;
    {
        int rr = ms * 16 + r;
        float u0[12], u1[12];
#pragma unroll
        for (int k = 0; k < 12; ++k) { u0[k] = us[rr * 12 + k]; u1[k] = us[(rr + 8) * 12 + k]; }
#pragma unroll
        for (int t = 0; t < 4; ++t) {
            int c0 = nq * 32 + t * 8 + q * 2;
            float x00 = 0.f, x01 = 0.f, x10 = 0.f, x11 = 0.f;
#pragma unroll
            for (int k = 0; k < 12; ++k) {
                float v0 = Vs[k * 128 + c0], v1 = Vs[k * 128 + c0 + 1];
                x00 = fmaf(u0[k], v0, x00); x01 = fmaf(u0[k], v1, x01);
                x10 = fmaf(u1[k], v0, x10); x11 = fmaf(u1[k], v1, x11);
            }
            float bbx = b2s[c0], bby = b2s[c0 + 1];
            ys[rr * 132 + c0]           = d[t][0] + bbx + x00;
            ys[rr * 132 + c0 + 1]       = d[t][1] + bby + x01;
            ys[(rr + 8) * 132 + c0]     = d[t][2] + bbx + x10;
            ys[(rr + 8) * 132 + c0 + 1] = d[t][3] + bby + x11;
        }
    }
    __syncthreads();

    // LN2: 8 warps x 4 rows
#pragma unroll
    for (int jj = 0; jj < 4; ++jj) {
        int rr = wid * 4 + jj;
        float z[4];
#pragma unroll
        for (int j = 0; j < 4; ++j) z[j] = ys[rr * 132 + lane + 32 * j];
        float s2 = z[0] + z[1] + z[2] + z[3];
#pragma unroll
        for (int o = 16; o > 0; o >>= 1) s2 += __shfl_xor_sync(0xffffffffu, s2, o);
        float mu = s2 * (1.0f / 128.0f);
        float v = 0.f;
#pragma unroll
        for (int j = 0; j < 4; ++j) { float dd = z[j] - mu; v += dd * dd; }
#pragma unroll
        for (int o = 16; o > 0; o >>= 1) v += __shfl_xor_sync(0xffffffffu, v, o);
        float rstd = rsqrtf(v * (1.0f / 128.0f) + 1e-5f);
#pragma unroll
        for (int j = 0; j < 4; ++j) {
            int c = lane + 32 * j;
            g_out2[(size_t)(row0 + rr) * 128 + c] = (z[j] - mu) * rstd * lgs[c] + lbs[c];
        }
    }
}

// ----- out[b,c,t] = sum_n out2[((b*32+n)*256+t)*128 + c]; float4 tree ------
__global__ void reduce_kernel(float *__restrict__ out) {
    __shared__ float4 sh[4 * 32];
    int t = blockIdx.x & 255, b = blockIdx.x >> 8;
    int c4 = threadIdx.x & 31, grp = threadIdx.x >> 5;
    const float *base = g_out2 + ((size_t)(b * 32 + grp * 4) * 256 + t) * 128 + c4 * 4;
    float4 acc = make_float4(0.f, 0.f, 0.f, 0.f);
#pragma unroll
    for (int n = 0; n < 4; ++n) {
        float4 v = *(const float4 *)(base + (size_t)n * 256 * 128);
        acc.x += v.x; acc.y += v.y; acc.z += v.z; acc.w += v.w;
    }
    if (grp >= 4) sh[(grp - 4) * 32 + c4] = acc;
    __syncthreads();
    if (grp < 4) {
        float4 v = sh[grp * 32 + c4];
        acc.x += v.x; acc.y += v.y; acc.z += v.z; acc.w += v.w;
    }
    __syncthreads();
    if (grp >= 2 && grp < 4) sh[(grp - 2) * 32 + c4] = acc;
    __syncthreads();
    if (grp < 2) {
        float4 v = sh[grp * 32 + c4];
        acc.x += v.x; acc.y += v.y; acc.z += v.z; acc.w += v.w;
    }
    __syncthreads();
    if (grp == 1) sh[c4] = acc;
    __syncthreads();
    if (grp == 0) {
        float4 v = sh[c4];
        acc.x += v.x; acc.y += v.y; acc.z += v.z; acc.w += v.w;
        int cb = c4 * 4;
        out[((b * 128 + cb + 0) << 8) + t] = acc.x;
        out[((b * 128 + cb + 1) << 8) + t] = acc.y;
        out[((b * 128 + cb + 2) << 8) + t] = acc.z;
        out[((b * 128 + cb + 3) << 8) + t] = acc.w;
    }
}

extern "C" void kernel_launch(void* const* d_in, const int* in_sizes, int n_in,
                              void* d_out, int out_size) {
    const float *x     = (const float *)d_in[0];
    const float *mlp_w = (const float *)d_in[1];
    const float *mlp_b = (const float *)d_in[2];
    const float *wq = (const float *)d_in[3],  *bq = (const float *)d_in[4];
    const float *wk = (const float *)d_in[5],  *bk = (const float *)d_in[6];
    const float *wv = (const float *)d_in[7],  *bv = (const float *)d_in[8];
    const float *wo = (const float *)d_in[9],  *bo = (const float *)d_in[10];
    const float *w1 = (const float *)d_in[11], *b1 = (const float *)d_in[12];
    const float *w2 = (const float *)d_in[13], *b2 = (const float *)d_in[14];
    const float *ln1g = (const float *)d_in[15], *ln1b = (const float *)d_in[16];
    const float *ln2g = (const float *)d_in[17], *ln2b = (const float *)d_in[18];
    float *out = (float *)d_out;

    setup_a<<<153, 256>>>(mlp_w, mlp_b, wq, bq, wk, bk, wv, bv, w2);
    setup_b<<<17, 256>>>(wo, bo);
    setup_c<<<15, 256>>>(mlp_w, mlp_b, ln1g, ln1b);
    setup_d<<<64, 256>>>(w1, b1);
    attn_kernel<<<128, 256>>>(x);
    ffn_kernel<<<TOK / 32, 256>>>(b2, ln2g, ln2b);
    reduce_kernel<<<4 * 256, 256>>>(out);
}